// round 10
// baseline (speedup 1.0000x reference)
#include <cuda_runtime.h>
#include <cstdint>
#include <math.h>

// GEMMs: exact fp32 (sufficient: logit noise enters KL with gain ~2e-3).
// PRNG: JAX partitionable threefry (bit-correct).
// Epilogue + final reductions: FLOAT64. The per-row KL is ~3e-5 assembled from
// O(1) exp/log values, so f32 epilogue rounding costs ~0.74e-3 output rel-err
// per implementation; ref and our f32 epilogues were two independent noise
// draws => observed sqrt(2)*0.74e-3 = 1.05e-3 floor. f64 on our side removes
// our half, leaving only ref's ~0.74e-3 < 1e-3 threshold.

// ---------------- problem constants ----------------
constexpr int NV = 12;                                // with, zeros, 10 cf
constexpr int R = 32 * 512 * 10;                      // 163840 rows
constexpr int MT = 64;                                // rows per tile
constexpr int NTILES = R / MT;                        // 2560
constexpr int STX = 132;
constexpr int STH = 68;

// ---------------- smem layout (floats) ----------------
constexpr int OFF_W1 = 0;                     // [144][128]
constexpr int OFF_W2 = OFF_W1 + 144 * 128;    // [128][64]
constexpr int OFF_W3 = OFF_W2 + 128 * 64;     // [64][16]
constexpr int OFF_B1 = OFF_W3 + 64 * 16;
constexpr int OFF_B2 = OFF_B1 + 128;
constexpr int OFF_B3 = OFF_B2 + 64;
constexpr int OFF_X  = OFF_B3 + 16;
constexpr int OFF_H1 = OFF_X + MT * STX;
constexpr int OFF_H2 = OFF_H1 + MT * STX;
constexpr int OFF_ACT = OFF_H2 + MT * STH;
constexpr int OFF_PW = OFF_ACT + MT * 16;
constexpr int OFF_PA = OFF_PW + MT * 16;
constexpr int SMEM_FLOATS = OFF_PA + MT * 16;
constexpr size_t SMEM_BYTES = SMEM_FLOATS * sizeof(float); // ~208 KB

__device__ double g_infl[R];

// ---------------- threefry2x32 (20 rounds, JAX-exact) ----------------
__device__ __forceinline__ void tf2x32(uint32_t k0, uint32_t k1,
                                       uint32_t c0, uint32_t c1,
                                       uint32_t& o0, uint32_t& o1) {
    uint32_t ks2 = k0 ^ k1 ^ 0x1BD11BDAu;
    uint32_t x0 = c0 + k0, x1 = c1 + k1;
#define TF_R(r) { x0 += x1; x1 = (x1 << (r)) | (x1 >> (32 - (r))); x1 ^= x0; }
    TF_R(13) TF_R(15) TF_R(26) TF_R(6)
    x0 += k1;  x1 += ks2 + 1u;
    TF_R(17) TF_R(29) TF_R(16) TF_R(24)
    x0 += ks2; x1 += k0 + 2u;
    TF_R(13) TF_R(15) TF_R(26) TF_R(6)
    x0 += k0;  x1 += k1 + 3u;
    TF_R(17) TF_R(29) TF_R(16) TF_R(24)
    x0 += k1;  x1 += ks2 + 4u;
    TF_R(13) TF_R(15) TF_R(26) TF_R(6)
    x0 += ks2; x1 += k0 + 5u;
#undef TF_R
    o0 = x0; o1 = x1;
}

__device__ __forceinline__ float u01(uint32_t bits) {
    return __uint_as_float((bits >> 9) | 0x3F800000u) - 1.0f;
}

// ---------------- fused kernel ----------------
__global__ __launch_bounds__(256, 1)
void fused_kernel(const float* __restrict__ obs, const float* __restrict__ actions,
                  const float* __restrict__ W1, const float* __restrict__ b1,
                  const float* __restrict__ W2, const float* __restrict__ b2,
                  const float* __restrict__ W3, const float* __restrict__ b3) {
    extern __shared__ float sm[];
    float* sW1 = sm + OFF_W1;
    float* sW2 = sm + OFF_W2;
    float* sW3 = sm + OFF_W3;
    float* sB1 = sm + OFF_B1;
    float* sB2 = sm + OFF_B2;
    float* sB3 = sm + OFF_B3;
    float* sX  = sm + OFF_X;
    float* sH1 = sm + OFF_H1;
    float* sH2 = sm + OFF_H2;
    float* sAct = sm + OFF_ACT;
    float* sPw = sm + OFF_PW;
    float* sPa = sm + OFF_PA;

    const int tid = threadIdx.x;

    {
        const float4* s; float4* d;
        s = (const float4*)W1; d = (float4*)sW1;
        for (int i = tid; i < 144 * 128 / 4; i += 256) d[i] = s[i];
        s = (const float4*)W2; d = (float4*)sW2;
        for (int i = tid; i < 128 * 64 / 4; i += 256) d[i] = s[i];
        s = (const float4*)W3; d = (float4*)sW3;
        for (int i = tid; i < 64 * 16 / 4; i += 256) d[i] = s[i];
        s = (const float4*)b1; d = (float4*)sB1;
        for (int i = tid; i < 32; i += 256) d[i] = s[i];
        s = (const float4*)b2; d = (float4*)sB2;
        if (tid < 16) d[tid] = s[tid];
        s = (const float4*)b3; d = (float4*)sB3;
        if (tid < 4) d[tid] = s[tid];
    }

    const int row0 = blockIdx.x * MT;

    for (int i = tid; i < MT * 32; i += 256) {
        int r = i >> 5, c4 = i & 31;
        float4 v = ((const float4*)obs)[(size_t)(row0 + r) * 32 + c4];
        *(float4*)&sX[r * STX + c4 * 4] = v;
    }
    __syncthreads();

    const int tx = tid & 15;
    const int ty = tid >> 4;

    // ---- GEMM1: h1_base = obs @ W1[:128] + b1 ----
    float acc[4][8];
#pragma unroll
    for (int i = 0; i < 4; i++)
#pragma unroll
        for (int j = 0; j < 8; j++) acc[i][j] = sB1[tx * 8 + j];

#pragma unroll 4
    for (int k = 0; k < 128; k++) {
        float a0 = sX[(ty * 4 + 0) * STX + k];
        float a1 = sX[(ty * 4 + 1) * STX + k];
        float a2 = sX[(ty * 4 + 2) * STX + k];
        float a3 = sX[(ty * 4 + 3) * STX + k];
        const float* wr = &sW1[k * 128 + tx * 8];
        float4 bA = *(const float4*)wr;
        float4 bB = *(const float4*)(wr + 4);
        float bj[8] = {bA.x, bA.y, bA.z, bA.w, bB.x, bB.y, bB.z, bB.w};
#pragma unroll
        for (int j = 0; j < 8; j++) {
            acc[0][j] += a0 * bj[j];
            acc[1][j] += a1 * bj[j];
            acc[2][j] += a2 * bj[j];
            acc[3][j] += a3 * bj[j];
        }
    }
    __syncthreads();
#pragma unroll
    for (int i = 0; i < 4; i++)
#pragma unroll
        for (int j = 0; j < 8; j++)
            sX[(ty * 4 + i) * STX + tx * 8 + j] = acc[i][j];
    __syncthreads();

    // ---- variant loop ----
    for (int v = 0; v < NV; v++) {
        if (v == 0) {
            for (int i = tid; i < MT * 16 / 4; i += 256)
                ((float4*)sAct)[i] = ((const float4*)actions)[(size_t)row0 * 4 + i];
        } else if (v == 1) {
            for (int i = tid; i < MT * 16; i += 256) sAct[i] = 0.0f;
        } else {
            uint32_t s = (uint32_t)(v - 2);
            uint32_t k0, k1;
            tf2x32(0u, 1u, 0u, s, k0, k1);   // key_s = threefry(key(1), (0,s))
            for (int i = tid; i < MT * 16; i += 256) {
                uint32_t gi = (uint32_t)row0 * 16u + (uint32_t)i;
                uint32_t o0, o1;
                tf2x32(k0, k1, 0u, gi, o0, o1);
                sAct[i] = u01(o0 ^ o1);
            }
        }
        __syncthreads();

        float d[4][8];
#pragma unroll
        for (int i = 0; i < 4; i++)
#pragma unroll
            for (int j = 0; j < 8; j++) d[i][j] = 0.0f;
#pragma unroll
        for (int k = 0; k < 16; k++) {
            float a0 = sAct[(ty * 4 + 0) * 16 + k];
            float a1 = sAct[(ty * 4 + 1) * 16 + k];
            float a2 = sAct[(ty * 4 + 2) * 16 + k];
            float a3 = sAct[(ty * 4 + 3) * 16 + k];
            const float* wr = &sW1[(128 + k) * 128 + tx * 8];
            float4 bA = *(const float4*)wr;
            float4 bB = *(const float4*)(wr + 4);
            float bj[8] = {bA.x, bA.y, bA.z, bA.w, bB.x, bB.y, bB.z, bB.w};
#pragma unroll
            for (int j = 0; j < 8; j++) {
                d[0][j] += a0 * bj[j];
                d[1][j] += a1 * bj[j];
                d[2][j] += a2 * bj[j];
                d[3][j] += a3 * bj[j];
            }
        }
#pragma unroll
        for (int i = 0; i < 4; i++)
#pragma unroll
            for (int j = 0; j < 8; j++) {
                float h = sX[(ty * 4 + i) * STX + tx * 8 + j] + d[i][j];
                sH1[(ty * 4 + i) * STX + tx * 8 + j] = fmaxf(h, 0.0f);
            }
        __syncthreads();

        float c2[4][4];
#pragma unroll
        for (int i = 0; i < 4; i++)
#pragma unroll
            for (int j = 0; j < 4; j++) c2[i][j] = sB2[tx * 4 + j];
#pragma unroll 4
        for (int k = 0; k < 128; k++) {
            float a0 = sH1[(ty * 4 + 0) * STX + k];
            float a1 = sH1[(ty * 4 + 1) * STX + k];
            float a2 = sH1[(ty * 4 + 2) * STX + k];
            float a3 = sH1[(ty * 4 + 3) * STX + k];
            float4 w = *(const float4*)&sW2[k * 64 + tx * 4];
            c2[0][0] += a0 * w.x; c2[0][1] += a0 * w.y; c2[0][2] += a0 * w.z; c2[0][3] += a0 * w.w;
            c2[1][0] += a1 * w.x; c2[1][1] += a1 * w.y; c2[1][2] += a1 * w.z; c2[1][3] += a1 * w.w;
            c2[2][0] += a2 * w.x; c2[2][1] += a2 * w.y; c2[2][2] += a2 * w.z; c2[2][3] += a2 * w.w;
            c2[3][0] += a3 * w.x; c2[3][1] += a3 * w.y; c2[3][2] += a3 * w.z; c2[3][3] += a3 * w.w;
        }
#pragma unroll
        for (int i = 0; i < 4; i++)
#pragma unroll
            for (int j = 0; j < 4; j++)
                sH2[(ty * 4 + i) * STH + tx * 4 + j] = fmaxf(c2[i][j], 0.0f);
        __syncthreads();

        {
            int rr = tid >> 2;
            int cg = (tid & 3) * 4;
            float p0 = sB3[cg + 0], p1 = sB3[cg + 1], p2 = sB3[cg + 2], p3 = sB3[cg + 3];
#pragma unroll 8
            for (int k = 0; k < 64; k++) {
                float a = sH2[rr * STH + k];
                float4 w = *(const float4*)&sW3[k * 16 + cg];
                p0 += a * w.x; p1 += a * w.y; p2 += a * w.z; p3 += a * w.w;
            }
            if (v == 0) {
                sPw[rr * 16 + cg + 0] = p0; sPw[rr * 16 + cg + 1] = p1;
                sPw[rr * 16 + cg + 2] = p2; sPw[rr * 16 + cg + 3] = p3;
            } else if (v == 1) {
                sPa[rr * 16 + cg + 0] = p0; sPa[rr * 16 + cg + 1] = p1;
                sPa[rr * 16 + cg + 2] = p2; sPa[rr * 16 + cg + 3] = p3;
            } else {
                sPa[rr * 16 + cg + 0] += p0;
                sPa[rr * 16 + cg + 1] += p1;
                sPa[rr * 16 + cg + 2] += p2;
                sPa[rr * 16 + cg + 3] += p3;
            }
        }
        __syncthreads();
    }

    // ---- epilogue: per-row KL term in FLOAT64 (removes our half of the
    //      mutual f32 epilogue-noise floor) ----
    if (tid < MT) {
        const int r = tid;
        double pw[16], po[16];
#pragma unroll
        for (int a = 0; a < 16; a++) {
            pw[a] = (double)sPw[r * 16 + a];
            po[a] = (double)sPa[r * 16 + a] / 11.0;
        }
        double mw = pw[0], mo = po[0];
#pragma unroll
        for (int a = 1; a < 16; a++) {
            mw = fmax(mw, pw[a]);
            mo = fmax(mo, po[a]);
        }
        double eo[16];
        double sw = 0.0, so = 0.0;
#pragma unroll
        for (int a = 0; a < 16; a++) {
            sw += exp(pw[a] - mw);
            eo[a] = exp(po[a] - mo);
            so += eo[a];
        }
        double lsw = log(sw);
        double infl = 0.0;
#pragma unroll
        for (int a = 0; a < 16; a++) {
            double q = eo[a] / so;
            double logq = log(q);
            double logp = (pw[a] - mw) - lsw;
            infl += q * (logq - logp);
        }
        g_infl[row0 + r] = infl;
    }
}

// ---------------- finalize: mean over N, normalize over T (f64) ----------------
__global__ void finalize_kernel(float* __restrict__ out) {
    const int b = blockIdx.x;
    const int tid = threadIdx.x;
    __shared__ double v[512];
    __shared__ double red[256];
    for (int t = tid; t < 512; t += 256) {
        const double* p = &g_infl[((size_t)b * 512 + t) * 10];
        double s = 0.0;
#pragma unroll
        for (int n = 0; n < 10; n++) s += p[n];
        v[t] = s;
    }
    __syncthreads();
    red[tid] = v[tid] + v[tid + 256];
    __syncthreads();
    for (int o = 128; o > 0; o >>= 1) {
        if (tid < o) red[tid] += red[tid + o];
        __syncthreads();
    }
    double tot = red[0];
    for (int t = tid; t < 512; t += 256)
        out[(size_t)b * 512 + t] = (float)(v[t] / tot);
}

// ---------------- launch ----------------
extern "C" void kernel_launch(void* const* d_in, const int* in_sizes, int n_in,
                              void* d_out, int out_size) {
    const float* obs     = (const float*)d_in[0];
    const float* actions = (const float*)d_in[1];
    const float* W1      = (const float*)d_in[2];
    const float* b1      = (const float*)d_in[3];
    const float* W2      = (const float*)d_in[4];
    const float* b2      = (const float*)d_in[5];
    const float* W3      = (const float*)d_in[6];
    const float* b3      = (const float*)d_in[7];

    cudaFuncSetAttribute(fused_kernel, cudaFuncAttributeMaxDynamicSharedMemorySize,
                         (int)SMEM_BYTES);
    fused_kernel<<<NTILES, 256, SMEM_BYTES>>>(obs, actions, W1, b1, W2, b2, W3, b3);
    finalize_kernel<<<32, 256>>>((float*)d_out);
}

// round 11
// speedup vs baseline: 1.0790x; 1.0790x over previous
#include <cuda_runtime.h>
#include <cstdint>
#include <math.h>

// Numerics (FROZEN — R10 passed at rel_err 7.0e-4):
//   GEMMs exact fp32, same per-accumulator k-order; PRNG JAX partitionable
//   threefry; epilogue + reductions in float64.
// R11 change: scalar FFMA -> packed fma.rn.f32x2 (Blackwell FFMA2), which is
// bit-identical (2 independent IEEE-rn FMAs) but doubles FMA-pipe throughput.

// ---------------- problem constants ----------------
constexpr int NV = 12;                                // with, zeros, 10 cf
constexpr int R = 32 * 512 * 10;                      // 163840 rows
constexpr int MT = 64;                                // rows per tile
constexpr int NTILES = R / MT;                        // 2560
constexpr int STX = 132;
constexpr int STH = 68;

// ---------------- smem layout (floats) ----------------
constexpr int OFF_W1 = 0;                     // [144][128]
constexpr int OFF_W2 = OFF_W1 + 144 * 128;    // [128][64]
constexpr int OFF_W3 = OFF_W2 + 128 * 64;     // [64][16]
constexpr int OFF_B1 = OFF_W3 + 64 * 16;
constexpr int OFF_B2 = OFF_B1 + 128;
constexpr int OFF_B3 = OFF_B2 + 64;
constexpr int OFF_X  = OFF_B3 + 16;
constexpr int OFF_H1 = OFF_X + MT * STX;
constexpr int OFF_H2 = OFF_H1 + MT * STX;
constexpr int OFF_ACT = OFF_H2 + MT * STH;
constexpr int OFF_PW = OFF_ACT + MT * 16;
constexpr int OFF_PA = OFF_PW + MT * 16;
constexpr int SMEM_FLOATS = OFF_PA + MT * 16;
constexpr size_t SMEM_BYTES = SMEM_FLOATS * sizeof(float); // ~208 KB

__device__ double g_infl[R];

// ---------------- packed f32x2 helpers (bit-identical to 2x scalar FFMA) ----
typedef unsigned long long u64t;

__device__ __forceinline__ u64t pk2(float lo, float hi) {
    u64t d;
    asm("mov.b64 %0, {%1, %2};" : "=l"(d)
        : "r"(__float_as_uint(lo)), "r"(__float_as_uint(hi)));
    return d;
}
__device__ __forceinline__ void upk2(float& lo, float& hi, u64t s) {
    uint32_t a, b;
    asm("mov.b64 {%0, %1}, %2;" : "=r"(a), "=r"(b) : "l"(s));
    lo = __uint_as_float(a);
    hi = __uint_as_float(b);
}
__device__ __forceinline__ u64t fma2(u64t a, u64t b, u64t c) {
    u64t d;
    asm("fma.rn.f32x2 %0, %1, %2, %3;" : "=l"(d) : "l"(a), "l"(b), "l"(c));
    return d;
}

// ---------------- threefry2x32 (20 rounds, JAX-exact) ----------------
__device__ __forceinline__ void tf2x32(uint32_t k0, uint32_t k1,
                                       uint32_t c0, uint32_t c1,
                                       uint32_t& o0, uint32_t& o1) {
    uint32_t ks2 = k0 ^ k1 ^ 0x1BD11BDAu;
    uint32_t x0 = c0 + k0, x1 = c1 + k1;
#define TF_R(r) { x0 += x1; x1 = (x1 << (r)) | (x1 >> (32 - (r))); x1 ^= x0; }
    TF_R(13) TF_R(15) TF_R(26) TF_R(6)
    x0 += k1;  x1 += ks2 + 1u;
    TF_R(17) TF_R(29) TF_R(16) TF_R(24)
    x0 += ks2; x1 += k0 + 2u;
    TF_R(13) TF_R(15) TF_R(26) TF_R(6)
    x0 += k0;  x1 += k1 + 3u;
    TF_R(17) TF_R(29) TF_R(16) TF_R(24)
    x0 += k1;  x1 += ks2 + 4u;
    TF_R(13) TF_R(15) TF_R(26) TF_R(6)
    x0 += ks2; x1 += k0 + 5u;
#undef TF_R
    o0 = x0; o1 = x1;
}

__device__ __forceinline__ float u01(uint32_t bits) {
    return __uint_as_float((bits >> 9) | 0x3F800000u) - 1.0f;
}

// ---------------- fused kernel ----------------
__global__ __launch_bounds__(256, 1)
void fused_kernel(const float* __restrict__ obs, const float* __restrict__ actions,
                  const float* __restrict__ W1, const float* __restrict__ b1,
                  const float* __restrict__ W2, const float* __restrict__ b2,
                  const float* __restrict__ W3, const float* __restrict__ b3) {
    extern __shared__ float sm[];
    float* sW1 = sm + OFF_W1;
    float* sW2 = sm + OFF_W2;
    float* sW3 = sm + OFF_W3;
    float* sB1 = sm + OFF_B1;
    float* sB2 = sm + OFF_B2;
    float* sB3 = sm + OFF_B3;
    float* sX  = sm + OFF_X;
    float* sH1 = sm + OFF_H1;
    float* sH2 = sm + OFF_H2;
    float* sAct = sm + OFF_ACT;
    float* sPw = sm + OFF_PW;
    float* sPa = sm + OFF_PA;

    const int tid = threadIdx.x;

    {
        const float4* s; float4* d;
        s = (const float4*)W1; d = (float4*)sW1;
        for (int i = tid; i < 144 * 128 / 4; i += 256) d[i] = s[i];
        s = (const float4*)W2; d = (float4*)sW2;
        for (int i = tid; i < 128 * 64 / 4; i += 256) d[i] = s[i];
        s = (const float4*)W3; d = (float4*)sW3;
        for (int i = tid; i < 64 * 16 / 4; i += 256) d[i] = s[i];
        s = (const float4*)b1; d = (float4*)sB1;
        for (int i = tid; i < 32; i += 256) d[i] = s[i];
        s = (const float4*)b2; d = (float4*)sB2;
        if (tid < 16) d[tid] = s[tid];
        s = (const float4*)b3; d = (float4*)sB3;
        if (tid < 4) d[tid] = s[tid];
    }

    const int row0 = blockIdx.x * MT;

    for (int i = tid; i < MT * 32; i += 256) {
        int r = i >> 5, c4 = i & 31;
        float4 v = ((const float4*)obs)[(size_t)(row0 + r) * 32 + c4];
        *(float4*)&sX[r * STX + c4 * 4] = v;
    }
    __syncthreads();

    const int tx = tid & 15;
    const int ty = tid >> 4;

    // ---- GEMM1: h1_base = obs @ W1[:128] + b1  (packed f32x2) ----
    u64t acc2[4][4];
    {
        u64t bp[4];
#pragma unroll
        for (int j = 0; j < 4; j++)
            bp[j] = pk2(sB1[tx * 8 + 2 * j], sB1[tx * 8 + 2 * j + 1]);
#pragma unroll
        for (int i = 0; i < 4; i++)
#pragma unroll
            for (int j = 0; j < 4; j++) acc2[i][j] = bp[j];
    }

#pragma unroll 4
    for (int k = 0; k < 128; k++) {
        float a0 = sX[(ty * 4 + 0) * STX + k];
        float a1 = sX[(ty * 4 + 1) * STX + k];
        float a2 = sX[(ty * 4 + 2) * STX + k];
        float a3 = sX[(ty * 4 + 3) * STX + k];
        const u64t* wp = (const u64t*)&sW1[k * 128 + tx * 8];
        u64t w0 = wp[0], w1 = wp[1], w2 = wp[2], w3 = wp[3];
        u64t p0 = pk2(a0, a0), p1 = pk2(a1, a1), p2 = pk2(a2, a2), p3 = pk2(a3, a3);
        acc2[0][0] = fma2(p0, w0, acc2[0][0]); acc2[0][1] = fma2(p0, w1, acc2[0][1]);
        acc2[0][2] = fma2(p0, w2, acc2[0][2]); acc2[0][3] = fma2(p0, w3, acc2[0][3]);
        acc2[1][0] = fma2(p1, w0, acc2[1][0]); acc2[1][1] = fma2(p1, w1, acc2[1][1]);
        acc2[1][2] = fma2(p1, w2, acc2[1][2]); acc2[1][3] = fma2(p1, w3, acc2[1][3]);
        acc2[2][0] = fma2(p2, w0, acc2[2][0]); acc2[2][1] = fma2(p2, w1, acc2[2][1]);
        acc2[2][2] = fma2(p2, w2, acc2[2][2]); acc2[2][3] = fma2(p2, w3, acc2[2][3]);
        acc2[3][0] = fma2(p3, w0, acc2[3][0]); acc2[3][1] = fma2(p3, w1, acc2[3][1]);
        acc2[3][2] = fma2(p3, w2, acc2[3][2]); acc2[3][3] = fma2(p3, w3, acc2[3][3]);
    }
    __syncthreads();
#pragma unroll
    for (int i = 0; i < 4; i++)
#pragma unroll
        for (int j = 0; j < 4; j++) {
            float lo, hi;
            upk2(lo, hi, acc2[i][j]);
            sX[(ty * 4 + i) * STX + tx * 8 + 2 * j]     = lo;
            sX[(ty * 4 + i) * STX + tx * 8 + 2 * j + 1] = hi;
        }
    __syncthreads();

    // ---- variant loop ----
    for (int v = 0; v < NV; v++) {
        if (v == 0) {
            for (int i = tid; i < MT * 16 / 4; i += 256)
                ((float4*)sAct)[i] = ((const float4*)actions)[(size_t)row0 * 4 + i];
        } else if (v == 1) {
            for (int i = tid; i < MT * 16; i += 256) sAct[i] = 0.0f;
        } else {
            uint32_t s = (uint32_t)(v - 2);
            uint32_t k0, k1;
            tf2x32(0u, 1u, 0u, s, k0, k1);   // key_s = threefry(key(1), (0,s))
            for (int i = tid; i < MT * 16; i += 256) {
                uint32_t gi = (uint32_t)row0 * 16u + (uint32_t)i;
                uint32_t o0, o1;
                tf2x32(k0, k1, 0u, gi, o0, o1);
                sAct[i] = u01(o0 ^ o1);
            }
        }
        __syncthreads();

        // delta = act @ W1[128:144] (packed), h1 = relu(h1_base + delta)
        u64t d2[4][4];
#pragma unroll
        for (int i = 0; i < 4; i++)
#pragma unroll
            for (int j = 0; j < 4; j++) d2[i][j] = 0ull;
#pragma unroll
        for (int k = 0; k < 16; k++) {
            float a0 = sAct[(ty * 4 + 0) * 16 + k];
            float a1 = sAct[(ty * 4 + 1) * 16 + k];
            float a2 = sAct[(ty * 4 + 2) * 16 + k];
            float a3 = sAct[(ty * 4 + 3) * 16 + k];
            const u64t* wp = (const u64t*)&sW1[(128 + k) * 128 + tx * 8];
            u64t w0 = wp[0], w1 = wp[1], w2 = wp[2], w3 = wp[3];
            u64t p0 = pk2(a0, a0), p1 = pk2(a1, a1), p2 = pk2(a2, a2), p3 = pk2(a3, a3);
            d2[0][0] = fma2(p0, w0, d2[0][0]); d2[0][1] = fma2(p0, w1, d2[0][1]);
            d2[0][2] = fma2(p0, w2, d2[0][2]); d2[0][3] = fma2(p0, w3, d2[0][3]);
            d2[1][0] = fma2(p1, w0, d2[1][0]); d2[1][1] = fma2(p1, w1, d2[1][1]);
            d2[1][2] = fma2(p1, w2, d2[1][2]); d2[1][3] = fma2(p1, w3, d2[1][3]);
            d2[2][0] = fma2(p2, w0, d2[2][0]); d2[2][1] = fma2(p2, w1, d2[2][1]);
            d2[2][2] = fma2(p2, w2, d2[2][2]); d2[2][3] = fma2(p2, w3, d2[2][3]);
            d2[3][0] = fma2(p3, w0, d2[3][0]); d2[3][1] = fma2(p3, w1, d2[3][1]);
            d2[3][2] = fma2(p3, w2, d2[3][2]); d2[3][3] = fma2(p3, w3, d2[3][3]);
        }
#pragma unroll
        for (int i = 0; i < 4; i++)
#pragma unroll
            for (int j = 0; j < 4; j++) {
                float lo, hi;
                upk2(lo, hi, d2[i][j]);
                float h0 = sX[(ty * 4 + i) * STX + tx * 8 + 2 * j]     + lo;
                float h1v = sX[(ty * 4 + i) * STX + tx * 8 + 2 * j + 1] + hi;
                sH1[(ty * 4 + i) * STX + tx * 8 + 2 * j]     = fmaxf(h0, 0.0f);
                sH1[(ty * 4 + i) * STX + tx * 8 + 2 * j + 1] = fmaxf(h1v, 0.0f);
            }
        __syncthreads();

        // GEMM2: h2 = relu(h1 @ W2 + b2)  (packed f32x2)
        u64t c22[4][2];
        {
            u64t b0 = pk2(sB2[tx * 4 + 0], sB2[tx * 4 + 1]);
            u64t b1p = pk2(sB2[tx * 4 + 2], sB2[tx * 4 + 3]);
#pragma unroll
            for (int i = 0; i < 4; i++) { c22[i][0] = b0; c22[i][1] = b1p; }
        }
#pragma unroll 4
        for (int k = 0; k < 128; k++) {
            float a0 = sH1[(ty * 4 + 0) * STX + k];
            float a1 = sH1[(ty * 4 + 1) * STX + k];
            float a2 = sH1[(ty * 4 + 2) * STX + k];
            float a3 = sH1[(ty * 4 + 3) * STX + k];
            const u64t* wp = (const u64t*)&sW2[k * 64 + tx * 4];
            u64t w0 = wp[0], w1 = wp[1];
            u64t p0 = pk2(a0, a0), p1 = pk2(a1, a1), p2 = pk2(a2, a2), p3 = pk2(a3, a3);
            c22[0][0] = fma2(p0, w0, c22[0][0]); c22[0][1] = fma2(p0, w1, c22[0][1]);
            c22[1][0] = fma2(p1, w0, c22[1][0]); c22[1][1] = fma2(p1, w1, c22[1][1]);
            c22[2][0] = fma2(p2, w0, c22[2][0]); c22[2][1] = fma2(p2, w1, c22[2][1]);
            c22[3][0] = fma2(p3, w0, c22[3][0]); c22[3][1] = fma2(p3, w1, c22[3][1]);
        }
#pragma unroll
        for (int i = 0; i < 4; i++)
#pragma unroll
            for (int j = 0; j < 2; j++) {
                float lo, hi;
                upk2(lo, hi, c22[i][j]);
                sH2[(ty * 4 + i) * STH + tx * 4 + 2 * j]     = fmaxf(lo, 0.0f);
                sH2[(ty * 4 + i) * STH + tx * 4 + 2 * j + 1] = fmaxf(hi, 0.0f);
            }
        __syncthreads();

        // GEMM3: p = h2 @ W3 + b3 (packed) ; accumulate
        {
            int rr = tid >> 2;
            int cg = (tid & 3) * 4;
            u64t q0 = pk2(sB3[cg + 0], sB3[cg + 1]);
            u64t q1 = pk2(sB3[cg + 2], sB3[cg + 3]);
#pragma unroll 8
            for (int k = 0; k < 64; k++) {
                float a = sH2[rr * STH + k];
                const u64t* wp = (const u64t*)&sW3[k * 16 + cg];
                u64t pa = pk2(a, a);
                q0 = fma2(pa, wp[0], q0);
                q1 = fma2(pa, wp[1], q1);
            }
            float p0, p1, p2, p3;
            upk2(p0, p1, q0);
            upk2(p2, p3, q1);
            if (v == 0) {
                sPw[rr * 16 + cg + 0] = p0; sPw[rr * 16 + cg + 1] = p1;
                sPw[rr * 16 + cg + 2] = p2; sPw[rr * 16 + cg + 3] = p3;
            } else if (v == 1) {
                sPa[rr * 16 + cg + 0] = p0; sPa[rr * 16 + cg + 1] = p1;
                sPa[rr * 16 + cg + 2] = p2; sPa[rr * 16 + cg + 3] = p3;
            } else {
                sPa[rr * 16 + cg + 0] += p0;
                sPa[rr * 16 + cg + 1] += p1;
                sPa[rr * 16 + cg + 2] += p2;
                sPa[rr * 16 + cg + 3] += p3;
            }
        }
        __syncthreads();
    }

    // ---- epilogue: per-row KL term in FLOAT64 ----
    if (tid < MT) {
        const int r = tid;
        double pw[16], po[16];
#pragma unroll
        for (int a = 0; a < 16; a++) {
            pw[a] = (double)sPw[r * 16 + a];
            po[a] = (double)sPa[r * 16 + a] / 11.0;
        }
        double mw = pw[0], mo = po[0];
#pragma unroll
        for (int a = 1; a < 16; a++) {
            mw = fmax(mw, pw[a]);
            mo = fmax(mo, po[a]);
        }
        double eo[16];
        double sw = 0.0, so = 0.0;
#pragma unroll
        for (int a = 0; a < 16; a++) {
            sw += exp(pw[a] - mw);
            eo[a] = exp(po[a] - mo);
            so += eo[a];
        }
        double lsw = log(sw);
        double infl = 0.0;
#pragma unroll
        for (int a = 0; a < 16; a++) {
            double q = eo[a] / so;
            double logq = log(q);
            double logp = (pw[a] - mw) - lsw;
            infl += q * (logq - logp);
        }
        g_infl[row0 + r] = infl;
    }
}

// ---------------- finalize: mean over N, normalize over T (f64) ----------------
__global__ void finalize_kernel(float* __restrict__ out) {
    const int b = blockIdx.x;
    const int tid = threadIdx.x;
    __shared__ double v[512];
    __shared__ double red[256];
    for (int t = tid; t < 512; t += 256) {
        const double* p = &g_infl[((size_t)b * 512 + t) * 10];
        double s = 0.0;
#pragma unroll
        for (int n = 0; n < 10; n++) s += p[n];
        v[t] = s;
    }
    __syncthreads();
    red[tid] = v[tid] + v[tid + 256];
    __syncthreads();
    for (int o = 128; o > 0; o >>= 1) {
        if (tid < o) red[tid] += red[tid + o];
        __syncthreads();
    }
    double tot = red[0];
    for (int t = tid; t < 512; t += 256)
        out[(size_t)b * 512 + t] = (float)(v[t] / tot);
}

// ---------------- launch ----------------
extern "C" void kernel_launch(void* const* d_in, const int* in_sizes, int n_in,
                              void* d_out, int out_size) {
    const float* obs     = (const float*)d_in[0];
    const float* actions = (const float*)d_in[1];
    const float* W1      = (const float*)d_in[2];
    const float* b1      = (const float*)d_in[3];
    const float* W2      = (const float*)d_in[4];
    const float* b2      = (const float*)d_in[5];
    const float* W3      = (const float*)d_in[6];
    const float* b3      = (const float*)d_in[7];

    cudaFuncSetAttribute(fused_kernel, cudaFuncAttributeMaxDynamicSharedMemorySize,
                         (int)SMEM_BYTES);
    fused_kernel<<<NTILES, 256, SMEM_BYTES>>>(obs, actions, W1, b1, W2, b2, W3, b3);
    finalize_kernel<<<32, 256>>>((float*)d_out);
}

// round 12
// speedup vs baseline: 1.1760x; 1.0899x over previous
#include <cuda_runtime.h>
#include <cstdint>
#include <math.h>

// Numerics: GEMM accumulation chains bit-FROZEN (fp32, same per-accumulator
// k-order, FFMA2 = 2 independent IEEE-rn FMAs). PRNG: JAX partitionable
// threefry. Epilogue: fast custom f64 (accuracy ~1e-13; epilogue need not
// bit-match — R10 showed residual 7.0e-4 is the reference's own f32 noise).

// ---------------- problem constants ----------------
constexpr int NV = 12;                                // with, zeros, 10 cf
constexpr int R = 32 * 512 * 10;                      // 163840 rows
constexpr int MT = 64;                                // rows per tile
constexpr int NTILES = R / MT;                        // 2560
constexpr int STX = 132;
constexpr int STH = 68;

// ---------------- smem layout (floats) ----------------
constexpr int OFF_W1 = 0;                     // [144][128]
constexpr int OFF_W2 = OFF_W1 + 144 * 128;    // [128][64]
constexpr int OFF_W3 = OFF_W2 + 128 * 64;     // [64][16]
constexpr int OFF_B1 = OFF_W3 + 64 * 16;
constexpr int OFF_B2 = OFF_B1 + 128;
constexpr int OFF_B3 = OFF_B2 + 64;
constexpr int OFF_X  = OFF_B3 + 16;           // obs tile [64][132]
constexpr int OFF_H1 = OFF_X + MT * STX;      // relu(h1) per variant [64][132]
constexpr int OFF_H2 = OFF_H1 + MT * STX;     // [64][68]
constexpr int OFF_ACT = OFF_H2 + MT * STH;    // [64][16]
constexpr int OFF_PW = OFF_ACT + MT * 16;
constexpr int OFF_PA = OFF_PW + MT * 16;
constexpr int SMEM_FLOATS = OFF_PA + MT * 16;
constexpr size_t SMEM_BYTES = SMEM_FLOATS * sizeof(float); // ~208 KB

__device__ double g_infl[R];

// ---------------- packed f32x2 helpers ----------------
typedef unsigned long long u64t;

__device__ __forceinline__ u64t pk2(float lo, float hi) {
    u64t d;
    asm("mov.b64 %0, {%1, %2};" : "=l"(d)
        : "r"(__float_as_uint(lo)), "r"(__float_as_uint(hi)));
    return d;
}
__device__ __forceinline__ void upk2(float& lo, float& hi, u64t s) {
    uint32_t a, b;
    asm("mov.b64 {%0, %1}, %2;" : "=r"(a), "=r"(b) : "l"(s));
    lo = __uint_as_float(a);
    hi = __uint_as_float(b);
}
__device__ __forceinline__ u64t fma2(u64t a, u64t b, u64t c) {
    u64t d;
    asm("fma.rn.f32x2 %0, %1, %2, %3;" : "=l"(d) : "l"(a), "l"(b), "l"(c));
    return d;
}

// ---------------- fast f64 exp/log (err ~1e-13, args bounded) ----------------
__device__ __forceinline__ double fexp(double x) {
    // x in [~-40, 0]
    double n = floor(fma(x, 1.4426950408889634, 0.5));
    double r = fma(n, -6.93147180369123816490e-01, x);   // ln2_hi
    r = fma(n, -1.90821492927058770002e-10, r);          // ln2_lo
    double p = 2.5052108385441718775e-8;                  // 1/11!
    p = fma(p, r, 2.7557319223985890653e-7);              // 1/10!
    p = fma(p, r, 2.7557319223985892511e-6);              // 1/9!
    p = fma(p, r, 2.4801587301587301566e-5);              // 1/8!
    p = fma(p, r, 1.9841269841269841253e-4);              // 1/7!
    p = fma(p, r, 1.3888888888888889419e-3);              // 1/6!
    p = fma(p, r, 8.3333333333333332177e-3);              // 1/5!
    p = fma(p, r, 4.1666666666666664354e-2);              // 1/4!
    p = fma(p, r, 1.6666666666666665741e-1);              // 1/3!
    p = fma(p, r, 5.0e-1);                                // 1/2!
    p = fma(p, r, 1.0);
    p = fma(p, r, 1.0);
    int ni = (int)n;
    double two_n = __longlong_as_double((long long)(1023 + ni) << 52);
    return p * two_n;
}

__device__ __forceinline__ double flog(double x) {
    // x in [~0.5, 32]
    long long b = __double_as_longlong(x);
    int e = (int)(b >> 52) - 1022;
    double m = __longlong_as_double((b & 0x000FFFFFFFFFFFFFLL) | 0x3FE0000000000000LL);
    if (m < 0.70710678118654752440) { m = m + m; e -= 1; }
    double f = m - 1.0;
    double s = f / (f + 2.0);
    double z = s * s;
    double p = 0.15384615384615385469;        // 2/13
    p = fma(p, z, 0.18181818181818182323);    // 2/11
    p = fma(p, z, 0.22222222222222220989);    // 2/9
    p = fma(p, z, 0.28571428571428569843);    // 2/7
    p = fma(p, z, 0.40000000000000002220);    // 2/5
    p = fma(p, z, 0.66666666666666662966);    // 2/3
    p = fma(p, z, 2.0);
    double lm = s * p;
    return fma((double)e, 0.69314718055994530942, lm);
}

// ---------------- threefry2x32 (20 rounds, JAX-exact) ----------------
__device__ __forceinline__ void tf2x32(uint32_t k0, uint32_t k1,
                                       uint32_t c0, uint32_t c1,
                                       uint32_t& o0, uint32_t& o1) {
    uint32_t ks2 = k0 ^ k1 ^ 0x1BD11BDAu;
    uint32_t x0 = c0 + k0, x1 = c1 + k1;
#define TF_R(r) { x0 += x1; x1 = (x1 << (r)) | (x1 >> (32 - (r))); x1 ^= x0; }
    TF_R(13) TF_R(15) TF_R(26) TF_R(6)
    x0 += k1;  x1 += ks2 + 1u;
    TF_R(17) TF_R(29) TF_R(16) TF_R(24)
    x0 += ks2; x1 += k0 + 2u;
    TF_R(13) TF_R(15) TF_R(26) TF_R(6)
    x0 += k0;  x1 += k1 + 3u;
    TF_R(17) TF_R(29) TF_R(16) TF_R(24)
    x0 += k1;  x1 += ks2 + 4u;
    TF_R(13) TF_R(15) TF_R(26) TF_R(6)
    x0 += ks2; x1 += k0 + 5u;
#undef TF_R
    o0 = x0; o1 = x1;
}

__device__ __forceinline__ float u01(uint32_t bits) {
    return __uint_as_float((bits >> 9) | 0x3F800000u) - 1.0f;
}

// ---------------- fused kernel ----------------
__global__ __launch_bounds__(256, 1)
void fused_kernel(const float* __restrict__ obs, const float* __restrict__ actions,
                  const float* __restrict__ W1, const float* __restrict__ b1,
                  const float* __restrict__ W2, const float* __restrict__ b2,
                  const float* __restrict__ W3, const float* __restrict__ b3) {
    extern __shared__ float sm[];
    float* sW1 = sm + OFF_W1;
    float* sW2 = sm + OFF_W2;
    float* sW3 = sm + OFF_W3;
    float* sB1 = sm + OFF_B1;
    float* sB2 = sm + OFF_B2;
    float* sB3 = sm + OFF_B3;
    float* sX  = sm + OFF_X;
    float* sH1 = sm + OFF_H1;
    float* sH2 = sm + OFF_H2;
    float* sAct = sm + OFF_ACT;
    float* sPw = sm + OFF_PW;
    float* sPa = sm + OFF_PA;

    const int tid = threadIdx.x;

    {
        const float4* s; float4* d;
        s = (const float4*)W1; d = (float4*)sW1;
        for (int i = tid; i < 144 * 128 / 4; i += 256) d[i] = s[i];
        s = (const float4*)W2; d = (float4*)sW2;
        for (int i = tid; i < 128 * 64 / 4; i += 256) d[i] = s[i];
        s = (const float4*)W3; d = (float4*)sW3;
        for (int i = tid; i < 64 * 16 / 4; i += 256) d[i] = s[i];
        s = (const float4*)b1; d = (float4*)sB1;
        for (int i = tid; i < 32; i += 256) d[i] = s[i];
        s = (const float4*)b2; d = (float4*)sB2;
        if (tid < 16) d[tid] = s[tid];
        s = (const float4*)b3; d = (float4*)sB3;
        if (tid < 4) d[tid] = s[tid];
    }

    const int row0 = blockIdx.x * MT;

    for (int i = tid; i < MT * 32; i += 256) {
        int r = i >> 5, c4 = i & 31;
        float4 v = ((const float4*)obs)[(size_t)(row0 + r) * 32 + c4];
        *(float4*)&sX[r * STX + c4 * 4] = v;
    }
    __syncthreads();

    const int tx = tid & 15;
    const int ty = tid >> 4;

    // ---- GEMM1: base = obs @ W1[:128] + b1 ; kept in REGISTERS ----
    u64t base2[4][4];
    {
        u64t bp[4];
#pragma unroll
        for (int j = 0; j < 4; j++)
            bp[j] = pk2(sB1[tx * 8 + 2 * j], sB1[tx * 8 + 2 * j + 1]);
#pragma unroll
        for (int i = 0; i < 4; i++)
#pragma unroll
            for (int j = 0; j < 4; j++) base2[i][j] = bp[j];
    }

    for (int k4 = 0; k4 < 128; k4 += 4) {
        float4 A0 = *(const float4*)&sX[(ty * 4 + 0) * STX + k4];
        float4 A1 = *(const float4*)&sX[(ty * 4 + 1) * STX + k4];
        float4 A2 = *(const float4*)&sX[(ty * 4 + 2) * STX + k4];
        float4 A3 = *(const float4*)&sX[(ty * 4 + 3) * STX + k4];
#pragma unroll
        for (int kk = 0; kk < 4; kk++) {
            const ulonglong2* wp = (const ulonglong2*)&sW1[(k4 + kk) * 128 + tx * 8];
            ulonglong2 wA = wp[0], wB = wp[1];
            float a0 = (&A0.x)[kk], a1 = (&A1.x)[kk], a2 = (&A2.x)[kk], a3 = (&A3.x)[kk];
            u64t p0 = pk2(a0, a0), p1 = pk2(a1, a1), p2 = pk2(a2, a2), p3 = pk2(a3, a3);
            base2[0][0] = fma2(p0, wA.x, base2[0][0]); base2[0][1] = fma2(p0, wA.y, base2[0][1]);
            base2[0][2] = fma2(p0, wB.x, base2[0][2]); base2[0][3] = fma2(p0, wB.y, base2[0][3]);
            base2[1][0] = fma2(p1, wA.x, base2[1][0]); base2[1][1] = fma2(p1, wA.y, base2[1][1]);
            base2[1][2] = fma2(p1, wB.x, base2[1][2]); base2[1][3] = fma2(p1, wB.y, base2[1][3]);
            base2[2][0] = fma2(p2, wA.x, base2[2][0]); base2[2][1] = fma2(p2, wA.y, base2[2][1]);
            base2[2][2] = fma2(p2, wB.x, base2[2][2]); base2[2][3] = fma2(p2, wB.y, base2[2][3]);
            base2[3][0] = fma2(p3, wA.x, base2[3][0]); base2[3][1] = fma2(p3, wA.y, base2[3][1]);
            base2[3][2] = fma2(p3, wB.x, base2[3][2]); base2[3][3] = fma2(p3, wB.y, base2[3][3]);
        }
    }
    // base stays in regs; sX (obs) no longer needed but not overwritten.

    // ---- variant loop ----
    for (int v = 0; v < NV; v++) {
        if (v == 0) {
            for (int i = tid; i < MT * 16 / 4; i += 256)
                ((float4*)sAct)[i] = ((const float4*)actions)[(size_t)row0 * 4 + i];
        } else if (v == 1) {
            for (int i = tid; i < MT * 16; i += 256) sAct[i] = 0.0f;
        } else {
            uint32_t s = (uint32_t)(v - 2);
            uint32_t k0, k1;
            tf2x32(0u, 1u, 0u, s, k0, k1);   // key_s = threefry(key(1), (0,s))
            for (int i = tid; i < MT * 16; i += 256) {
                uint32_t gi = (uint32_t)row0 * 16u + (uint32_t)i;
                uint32_t o0, o1;
                tf2x32(k0, k1, 0u, gi, o0, o1);
                sAct[i] = u01(o0 ^ o1);
            }
        }
        __syncthreads();

        // delta = act @ W1[128:144]; h1 = relu(base + delta) -> sH1
        u64t d2[4][4];
#pragma unroll
        for (int i = 0; i < 4; i++)
#pragma unroll
            for (int j = 0; j < 4; j++) d2[i][j] = 0ull;
#pragma unroll
        for (int k4 = 0; k4 < 16; k4 += 4) {
            float4 A0 = *(const float4*)&sAct[(ty * 4 + 0) * 16 + k4];
            float4 A1 = *(const float4*)&sAct[(ty * 4 + 1) * 16 + k4];
            float4 A2 = *(const float4*)&sAct[(ty * 4 + 2) * 16 + k4];
            float4 A3 = *(const float4*)&sAct[(ty * 4 + 3) * 16 + k4];
#pragma unroll
            for (int kk = 0; kk < 4; kk++) {
                const ulonglong2* wp = (const ulonglong2*)&sW1[(128 + k4 + kk) * 128 + tx * 8];
                ulonglong2 wA = wp[0], wB = wp[1];
                float a0 = (&A0.x)[kk], a1 = (&A1.x)[kk], a2 = (&A2.x)[kk], a3 = (&A3.x)[kk];
                u64t p0 = pk2(a0, a0), p1 = pk2(a1, a1), p2 = pk2(a2, a2), p3 = pk2(a3, a3);
                d2[0][0] = fma2(p0, wA.x, d2[0][0]); d2[0][1] = fma2(p0, wA.y, d2[0][1]);
                d2[0][2] = fma2(p0, wB.x, d2[0][2]); d2[0][3] = fma2(p0, wB.y, d2[0][3]);
                d2[1][0] = fma2(p1, wA.x, d2[1][0]); d2[1][1] = fma2(p1, wA.y, d2[1][1]);
                d2[1][2] = fma2(p1, wB.x, d2[1][2]); d2[1][3] = fma2(p1, wB.y, d2[1][3]);
                d2[2][0] = fma2(p2, wA.x, d2[2][0]); d2[2][1] = fma2(p2, wA.y, d2[2][1]);
                d2[2][2] = fma2(p2, wB.x, d2[2][2]); d2[2][3] = fma2(p2, wB.y, d2[2][3]);
                d2[3][0] = fma2(p3, wA.x, d2[3][0]); d2[3][1] = fma2(p3, wA.y, d2[3][1]);
                d2[3][2] = fma2(p3, wB.x, d2[3][2]); d2[3][3] = fma2(p3, wB.y, d2[3][3]);
            }
        }
#pragma unroll
        for (int i = 0; i < 4; i++)
#pragma unroll
            for (int j = 0; j < 4; j++) {
                float blo, bhi, dlo, dhi;
                upk2(blo, bhi, base2[i][j]);
                upk2(dlo, dhi, d2[i][j]);
                sH1[(ty * 4 + i) * STX + tx * 8 + 2 * j]     = fmaxf(blo + dlo, 0.0f);
                sH1[(ty * 4 + i) * STX + tx * 8 + 2 * j + 1] = fmaxf(bhi + dhi, 0.0f);
            }
        __syncthreads();

        // GEMM2: h2 = relu(h1 @ W2 + b2)
        u64t c22[4][2];
        {
            u64t b0 = pk2(sB2[tx * 4 + 0], sB2[tx * 4 + 1]);
            u64t b1p = pk2(sB2[tx * 4 + 2], sB2[tx * 4 + 3]);
#pragma unroll
            for (int i = 0; i < 4; i++) { c22[i][0] = b0; c22[i][1] = b1p; }
        }
        for (int k4 = 0; k4 < 128; k4 += 4) {
            float4 A0 = *(const float4*)&sH1[(ty * 4 + 0) * STX + k4];
            float4 A1 = *(const float4*)&sH1[(ty * 4 + 1) * STX + k4];
            float4 A2 = *(const float4*)&sH1[(ty * 4 + 2) * STX + k4];
            float4 A3 = *(const float4*)&sH1[(ty * 4 + 3) * STX + k4];
#pragma unroll
            for (int kk = 0; kk < 4; kk++) {
                ulonglong2 w = *(const ulonglong2*)&sW2[(k4 + kk) * 64 + tx * 4];
                float a0 = (&A0.x)[kk], a1 = (&A1.x)[kk], a2 = (&A2.x)[kk], a3 = (&A3.x)[kk];
                u64t p0 = pk2(a0, a0), p1 = pk2(a1, a1), p2 = pk2(a2, a2), p3 = pk2(a3, a3);
                c22[0][0] = fma2(p0, w.x, c22[0][0]); c22[0][1] = fma2(p0, w.y, c22[0][1]);
                c22[1][0] = fma2(p1, w.x, c22[1][0]); c22[1][1] = fma2(p1, w.y, c22[1][1]);
                c22[2][0] = fma2(p2, w.x, c22[2][0]); c22[2][1] = fma2(p2, w.y, c22[2][1]);
                c22[3][0] = fma2(p3, w.x, c22[3][0]); c22[3][1] = fma2(p3, w.y, c22[3][1]);
            }
        }
#pragma unroll
        for (int i = 0; i < 4; i++)
#pragma unroll
            for (int j = 0; j < 2; j++) {
                float lo, hi;
                upk2(lo, hi, c22[i][j]);
                sH2[(ty * 4 + i) * STH + tx * 4 + 2 * j]     = fmaxf(lo, 0.0f);
                sH2[(ty * 4 + i) * STH + tx * 4 + 2 * j + 1] = fmaxf(hi, 0.0f);
            }
        __syncthreads();

        // GEMM3: p = h2 @ W3 + b3 ; accumulate
        {
            int rr = tid >> 2;
            int cg = (tid & 3) * 4;
            u64t q0 = pk2(sB3[cg + 0], sB3[cg + 1]);
            u64t q1 = pk2(sB3[cg + 2], sB3[cg + 3]);
            for (int k4 = 0; k4 < 64; k4 += 4) {
                float4 av = *(const float4*)&sH2[rr * STH + k4];
#pragma unroll
                for (int kk = 0; kk < 4; kk++) {
                    ulonglong2 w = *(const ulonglong2*)&sW3[(k4 + kk) * 16 + cg];
                    float a = (&av.x)[kk];
                    u64t pa = pk2(a, a);
                    q0 = fma2(pa, w.x, q0);
                    q1 = fma2(pa, w.y, q1);
                }
            }
            float p0, p1, p2, p3;
            upk2(p0, p1, q0);
            upk2(p2, p3, q1);
            if (v == 0) {
                sPw[rr * 16 + cg + 0] = p0; sPw[rr * 16 + cg + 1] = p1;
                sPw[rr * 16 + cg + 2] = p2; sPw[rr * 16 + cg + 3] = p3;
            } else if (v == 1) {
                sPa[rr * 16 + cg + 0] = p0; sPa[rr * 16 + cg + 1] = p1;
                sPa[rr * 16 + cg + 2] = p2; sPa[rr * 16 + cg + 3] = p3;
            } else {
                sPa[rr * 16 + cg + 0] += p0;
                sPa[rr * 16 + cg + 1] += p1;
                sPa[rr * 16 + cg + 2] += p2;
                sPa[rr * 16 + cg + 3] += p3;
            }
        }
        __syncthreads();
    }

    // ---- epilogue: per-row KL in f64 (fast exp/log, algebraic logq) ----
    if (tid < MT) {
        const int r = tid;
        const double INV11 = 1.0 / 11.0;
        double pw[16], po[16];
#pragma unroll
        for (int a = 0; a < 16; a++) {
            pw[a] = (double)sPw[r * 16 + a];
            po[a] = (double)sPa[r * 16 + a] * INV11;
        }
        double mw = pw[0], mo = po[0];
#pragma unroll
        for (int a = 1; a < 16; a++) {
            mw = fmax(mw, pw[a]);
            mo = fmax(mo, po[a]);
        }
        double eo[16];
        double sw = 0.0, so = 0.0;
#pragma unroll
        for (int a = 0; a < 16; a++) {
            sw += fexp(pw[a] - mw);
            eo[a] = fexp(po[a] - mo);
            so += eo[a];
        }
        double lsw = flog(sw);
        double lso = flog(so);
        double inv_so = 1.0 / so;
        double infl = 0.0;
#pragma unroll
        for (int a = 0; a < 16; a++) {
            double q = eo[a] * inv_so;
            double logq = (po[a] - mo) - lso;
            double logp = (pw[a] - mw) - lsw;
            infl += q * (logq - logp);
        }
        g_infl[row0 + r] = infl;
    }
}

// ---------------- finalize: mean over N, normalize over T (f64) ----------------
__global__ void finalize_kernel(float* __restrict__ out) {
    const int b = blockIdx.x;
    const int tid = threadIdx.x;
    __shared__ double v[512];
    __shared__ double red[256];
    for (int t = tid; t < 512; t += 256) {
        const double* p = &g_infl[((size_t)b * 512 + t) * 10];
        double s = 0.0;
#pragma unroll
        for (int n = 0; n < 10; n++) s += p[n];
        v[t] = s;
    }
    __syncthreads();
    red[tid] = v[tid] + v[tid + 256];
    __syncthreads();
    for (int o = 128; o > 0; o >>= 1) {
        if (tid < o) red[tid] += red[tid + o];
        __syncthreads();
    }
    double tot = red[0];
    for (int t = tid; t < 512; t += 256)
        out[(size_t)b * 512 + t] = (float)(v[t] / tot);
}

// ---------------- launch ----------------
extern "C" void kernel_launch(void* const* d_in, const int* in_sizes, int n_in,
                              void* d_out, int out_size) {
    const float* obs     = (const float*)d_in[0];
    const float* actions = (const float*)d_in[1];
    const float* W1      = (const float*)d_in[2];
    const float* b1      = (const float*)d_in[3];
    const float* W2      = (const float*)d_in[4];
    const float* b2      = (const float*)d_in[5];
    const float* W3      = (const float*)d_in[6];
    const float* b3      = (const float*)d_in[7];

    cudaFuncSetAttribute(fused_kernel, cudaFuncAttributeMaxDynamicSharedMemorySize,
                         (int)SMEM_BYTES);
    fused_kernel<<<NTILES, 256, SMEM_BYTES>>>(obs, actions, W1, b1, W2, b2, W3, b3);
    finalize_kernel<<<32, 256>>>((float*)d_out);
}

// round 14
// speedup vs baseline: 1.2830x; 1.0910x over previous
#include <cuda_runtime.h>
#include <cstdint>
#include <math.h>

// Numerics: GEMM1/delta/GEMM3 bit-frozen scalar fp32 chains. GEMM2 runs on
// tensor cores via mma.sync m16n8k8 tf32 with 3xTF32 operand splitting
// (error ~1e-7 on logits -> ~2e-6 on output; measured ref-noise floor 0.70e-3,
// threshold 1e-3). PRNG: JAX partitionable threefry. Epilogue: fast f64.
// (Resubmission of R13 — prior bench failed on container acquisition, not code.)

// ---------------- problem constants ----------------
constexpr int NV = 12;
constexpr int R = 32 * 512 * 10;                      // 163840 rows
constexpr int MT = 64;
constexpr int NTILES = R / MT;                        // 2560
constexpr int STX = 132;
constexpr int STH = 68;

// ---------------- smem layout (floats) ----------------
constexpr int OFF_W1 = 0;                     // [144][128]; rows0-127 reused post-GEMM1
constexpr int OFF_W2 = OFF_W1 + 144 * 128;
constexpr int OFF_W3 = OFF_W2 + 128 * 64;
constexpr int OFF_B1 = OFF_W3 + 64 * 16;
constexpr int OFF_B2 = OFF_B1 + 128;
constexpr int OFF_B3 = OFF_B2 + 64;
constexpr int OFF_X  = OFF_B3 + 16;           // obs tile [64][132]; reused as W2bigT
constexpr int OFF_H1 = OFF_X + MT * STX;
constexpr int OFF_H2 = OFF_H1 + MT * STX;
constexpr int OFF_ACT = OFF_H2 + MT * STH;
constexpr int OFF_PW = OFF_ACT + MT * 16;
constexpr int OFF_PA = OFF_PW + MT * 16;
constexpr int SMEM_FLOATS = OFF_PA + MT * 16;
constexpr size_t SMEM_BYTES = SMEM_FLOATS * sizeof(float); // ~208 KB

__device__ double g_infl[R];

// ---------------- packed f32x2 helpers ----------------
typedef unsigned long long u64t;

__device__ __forceinline__ u64t pk2(float lo, float hi) {
    u64t d;
    asm("mov.b64 %0, {%1, %2};" : "=l"(d)
        : "r"(__float_as_uint(lo)), "r"(__float_as_uint(hi)));
    return d;
}
__device__ __forceinline__ void upk2(float& lo, float& hi, u64t s) {
    uint32_t a, b;
    asm("mov.b64 {%0, %1}, %2;" : "=r"(a), "=r"(b) : "l"(s));
    lo = __uint_as_float(a);
    hi = __uint_as_float(b);
}
__device__ __forceinline__ u64t fma2(u64t a, u64t b, u64t c) {
    u64t d;
    asm("fma.rn.f32x2 %0, %1, %2, %3;" : "=l"(d) : "l"(a), "l"(b), "l"(c));
    return d;
}

// ---------------- tf32 helpers ----------------
__device__ __forceinline__ float tf32rna(float x) {
    uint32_t u;
    asm("cvt.rna.tf32.f32 %0, %1;" : "=r"(u) : "f"(x));
    return __uint_as_float(u);
}

// mma.sync m16n8k8 tf32: d += a*b (f32 accumulate)
__device__ __forceinline__ void mma_tf32(float* d,
                                         uint32_t a0, uint32_t a1, uint32_t a2, uint32_t a3,
                                         uint32_t b0, uint32_t b1) {
    asm volatile(
        "mma.sync.aligned.m16n8k8.row.col.f32.tf32.tf32.f32 "
        "{%0,%1,%2,%3}, {%4,%5,%6,%7}, {%8,%9}, {%0,%1,%2,%3};"
        : "+f"(d[0]), "+f"(d[1]), "+f"(d[2]), "+f"(d[3])
        : "r"(a0), "r"(a1), "r"(a2), "r"(a3), "r"(b0), "r"(b1));
}

// ---------------- fast f64 exp/log (err ~1e-13, args bounded) ----------------
__device__ __forceinline__ double fexp(double x) {
    double n = floor(fma(x, 1.4426950408889634, 0.5));
    double r = fma(n, -6.93147180369123816490e-01, x);
    r = fma(n, -1.90821492927058770002e-10, r);
    double p = 2.5052108385441718775e-8;
    p = fma(p, r, 2.7557319223985890653e-7);
    p = fma(p, r, 2.7557319223985892511e-6);
    p = fma(p, r, 2.4801587301587301566e-5);
    p = fma(p, r, 1.9841269841269841253e-4);
    p = fma(p, r, 1.3888888888888889419e-3);
    p = fma(p, r, 8.3333333333333332177e-3);
    p = fma(p, r, 4.1666666666666664354e-2);
    p = fma(p, r, 1.6666666666666665741e-1);
    p = fma(p, r, 5.0e-1);
    p = fma(p, r, 1.0);
    p = fma(p, r, 1.0);
    int ni = (int)n;
    double two_n = __longlong_as_double((long long)(1023 + ni) << 52);
    return p * two_n;
}

__device__ __forceinline__ double flog(double x) {
    long long b = __double_as_longlong(x);
    int e = (int)(b >> 52) - 1022;
    double m = __longlong_as_double((b & 0x000FFFFFFFFFFFFFLL) | 0x3FE0000000000000LL);
    if (m < 0.70710678118654752440) { m = m + m; e -= 1; }
    double f = m - 1.0;
    double s = f / (f + 2.0);
    double z = s * s;
    double p = 0.15384615384615385469;
    p = fma(p, z, 0.18181818181818182323);
    p = fma(p, z, 0.22222222222222220989);
    p = fma(p, z, 0.28571428571428569843);
    p = fma(p, z, 0.40000000000000002220);
    p = fma(p, z, 0.66666666666666662966);
    p = fma(p, z, 2.0);
    double lm = s * p;
    return fma((double)e, 0.69314718055994530942, lm);
}

// ---------------- threefry2x32 (20 rounds, JAX-exact) ----------------
__device__ __forceinline__ void tf2x32(uint32_t k0, uint32_t k1,
                                       uint32_t c0, uint32_t c1,
                                       uint32_t& o0, uint32_t& o1) {
    uint32_t ks2 = k0 ^ k1 ^ 0x1BD11BDAu;
    uint32_t x0 = c0 + k0, x1 = c1 + k1;
#define TF_R(r) { x0 += x1; x1 = (x1 << (r)) | (x1 >> (32 - (r))); x1 ^= x0; }
    TF_R(13) TF_R(15) TF_R(26) TF_R(6)
    x0 += k1;  x1 += ks2 + 1u;
    TF_R(17) TF_R(29) TF_R(16) TF_R(24)
    x0 += ks2; x1 += k0 + 2u;
    TF_R(13) TF_R(15) TF_R(26) TF_R(6)
    x0 += k0;  x1 += k1 + 3u;
    TF_R(17) TF_R(29) TF_R(16) TF_R(24)
    x0 += k1;  x1 += ks2 + 4u;
    TF_R(13) TF_R(15) TF_R(26) TF_R(6)
    x0 += ks2; x1 += k0 + 5u;
#undef TF_R
    o0 = x0; o1 = x1;
}

__device__ __forceinline__ float u01(uint32_t bits) {
    return __uint_as_float((bits >> 9) | 0x3F800000u) - 1.0f;
}

// ---------------- fused kernel ----------------
__global__ __launch_bounds__(256, 1)
void fused_kernel(const float* __restrict__ obs, const float* __restrict__ actions,
                  const float* __restrict__ W1, const float* __restrict__ b1,
                  const float* __restrict__ W2, const float* __restrict__ b2,
                  const float* __restrict__ W3, const float* __restrict__ b3) {
    extern __shared__ float sm[];
    float* sW1 = sm + OFF_W1;
    float* sW2 = sm + OFF_W2;
    float* sW3 = sm + OFF_W3;
    float* sB1 = sm + OFF_B1;
    float* sB2 = sm + OFF_B2;
    float* sB3 = sm + OFF_B3;
    float* sX  = sm + OFF_X;
    float* sH1 = sm + OFF_H1;
    float* sH2 = sm + OFF_H2;
    float* sAct = sm + OFF_ACT;
    float* sPw = sm + OFF_PW;
    float* sPa = sm + OFF_PA;
    // post-GEMM1 reuse: W2 split/transposed [col][k] stride 132
    float* W2bigT = sX;            // 64*132 = 8448 floats (obs dead after GEMM1)
    float* W2smlT = sW1;           // first 8448 floats of W1 rows 0..127 (dead)

    const int tid = threadIdx.x;

    {
        const float4* s; float4* d;
        s = (const float4*)W1; d = (float4*)sW1;
        for (int i = tid; i < 144 * 128 / 4; i += 256) d[i] = s[i];
        s = (const float4*)W2; d = (float4*)sW2;
        for (int i = tid; i < 128 * 64 / 4; i += 256) d[i] = s[i];
        s = (const float4*)W3; d = (float4*)sW3;
        for (int i = tid; i < 64 * 16 / 4; i += 256) d[i] = s[i];
        s = (const float4*)b1; d = (float4*)sB1;
        for (int i = tid; i < 32; i += 256) d[i] = s[i];
        s = (const float4*)b2; d = (float4*)sB2;
        if (tid < 16) d[tid] = s[tid];
        s = (const float4*)b3; d = (float4*)sB3;
        if (tid < 4) d[tid] = s[tid];
    }

    const int row0 = blockIdx.x * MT;

    for (int i = tid; i < MT * 32; i += 256) {
        int r = i >> 5, c4 = i & 31;
        float4 v = ((const float4*)obs)[(size_t)(row0 + r) * 32 + c4];
        *(float4*)&sX[r * STX + c4 * 4] = v;
    }
    __syncthreads();

    const int tx = tid & 15;
    const int ty = tid >> 4;
    const int wid = tid >> 5;
    const int lane = tid & 31;
    const int g = lane >> 2;      // mma group id
    const int t4 = lane & 3;      // mma thread-in-group

    // ---- GEMM1: base = obs @ W1[:128] + b1 ; kept in REGISTERS (bit-frozen) ----
    u64t base2[4][4];
    {
        u64t bp[4];
#pragma unroll
        for (int j = 0; j < 4; j++)
            bp[j] = pk2(sB1[tx * 8 + 2 * j], sB1[tx * 8 + 2 * j + 1]);
#pragma unroll
        for (int i = 0; i < 4; i++)
#pragma unroll
            for (int j = 0; j < 4; j++) base2[i][j] = bp[j];
    }

    for (int k4 = 0; k4 < 128; k4 += 4) {
        float4 A0 = *(const float4*)&sX[(ty * 4 + 0) * STX + k4];
        float4 A1 = *(const float4*)&sX[(ty * 4 + 1) * STX + k4];
        float4 A2 = *(const float4*)&sX[(ty * 4 + 2) * STX + k4];
        float4 A3 = *(const float4*)&sX[(ty * 4 + 3) * STX + k4];
#pragma unroll
        for (int kk = 0; kk < 4; kk++) {
            const ulonglong2* wp = (const ulonglong2*)&sW1[(k4 + kk) * 128 + tx * 8];
            ulonglong2 wA = wp[0], wB = wp[1];
            float a0 = (&A0.x)[kk], a1 = (&A1.x)[kk], a2 = (&A2.x)[kk], a3 = (&A3.x)[kk];
            u64t p0 = pk2(a0, a0), p1 = pk2(a1, a1), p2 = pk2(a2, a2), p3 = pk2(a3, a3);
            base2[0][0] = fma2(p0, wA.x, base2[0][0]); base2[0][1] = fma2(p0, wA.y, base2[0][1]);
            base2[0][2] = fma2(p0, wB.x, base2[0][2]); base2[0][3] = fma2(p0, wB.y, base2[0][3]);
            base2[1][0] = fma2(p1, wA.x, base2[1][0]); base2[1][1] = fma2(p1, wA.y, base2[1][1]);
            base2[1][2] = fma2(p1, wB.x, base2[1][2]); base2[1][3] = fma2(p1, wB.y, base2[1][3]);
            base2[2][0] = fma2(p2, wA.x, base2[2][0]); base2[2][1] = fma2(p2, wA.y, base2[2][1]);
            base2[2][2] = fma2(p2, wB.x, base2[2][2]); base2[2][3] = fma2(p2, wB.y, base2[2][3]);
            base2[3][0] = fma2(p3, wA.x, base2[3][0]); base2[3][1] = fma2(p3, wA.y, base2[3][1]);
            base2[3][2] = fma2(p3, wB.x, base2[3][2]); base2[3][3] = fma2(p3, wB.y, base2[3][3]);
        }
    }
    __syncthreads();   // everyone done reading sX (obs) and sW1 rows 0-127

    // ---- split + transpose W2 -> W2bigT/W2smlT [col][k], stride 132 ----
    for (int idx = tid; idx < 128 * 64; idx += 256) {
        int k = idx >> 6, c = idx & 63;
        float w = sW2[k * 64 + c];
        float big = tf32rna(w);
        float sml = tf32rna(w - big);
        W2bigT[c * 132 + k] = big;
        W2smlT[c * 132 + k] = sml;
    }
    __syncthreads();

    // mma tiling for GEMM2: warp -> rows m0..m0+15, cols n0..n0+31
    const int m0 = (wid & 3) * 16;
    const int n0 = (wid >> 2) * 32;

    // ---- variant loop ----
    for (int v = 0; v < NV; v++) {
        if (v == 0) {
            for (int i = tid; i < MT * 16 / 4; i += 256)
                ((float4*)sAct)[i] = ((const float4*)actions)[(size_t)row0 * 4 + i];
        } else if (v == 1) {
            for (int i = tid; i < MT * 16; i += 256) sAct[i] = 0.0f;
        } else {
            uint32_t s = (uint32_t)(v - 2);
            uint32_t k0, k1;
            tf2x32(0u, 1u, 0u, s, k0, k1);
            for (int i = tid; i < MT * 16; i += 256) {
                uint32_t gi = (uint32_t)row0 * 16u + (uint32_t)i;
                uint32_t o0, o1;
                tf2x32(k0, k1, 0u, gi, o0, o1);
                sAct[i] = u01(o0 ^ o1);
            }
        }
        __syncthreads();

        // delta = act @ W1[128:144]; h1 = relu(base + delta) -> sH1 (bit-frozen)
        u64t d2[4][4];
#pragma unroll
        for (int i = 0; i < 4; i++)
#pragma unroll
            for (int j = 0; j < 4; j++) d2[i][j] = 0ull;
#pragma unroll
        for (int k4 = 0; k4 < 16; k4 += 4) {
            float4 A0 = *(const float4*)&sAct[(ty * 4 + 0) * 16 + k4];
            float4 A1 = *(const float4*)&sAct[(ty * 4 + 1) * 16 + k4];
            float4 A2 = *(const float4*)&sAct[(ty * 4 + 2) * 16 + k4];
            float4 A3 = *(const float4*)&sAct[(ty * 4 + 3) * 16 + k4];
#pragma unroll
            for (int kk = 0; kk < 4; kk++) {
                const ulonglong2* wp = (const ulonglong2*)&sW1[(128 + k4 + kk) * 128 + tx * 8];
                ulonglong2 wA = wp[0], wB = wp[1];
                float a0 = (&A0.x)[kk], a1 = (&A1.x)[kk], a2 = (&A2.x)[kk], a3 = (&A3.x)[kk];
                u64t p0 = pk2(a0, a0), p1 = pk2(a1, a1), p2 = pk2(a2, a2), p3 = pk2(a3, a3);
                d2[0][0] = fma2(p0, wA.x, d2[0][0]); d2[0][1] = fma2(p0, wA.y, d2[0][1]);
                d2[0][2] = fma2(p0, wB.x, d2[0][2]); d2[0][3] = fma2(p0, wB.y, d2[0][3]);
                d2[1][0] = fma2(p1, wA.x, d2[1][0]); d2[1][1] = fma2(p1, wA.y, d2[1][1]);
                d2[1][2] = fma2(p1, wB.x, d2[1][2]); d2[1][3] = fma2(p1, wB.y, d2[1][3]);
                d2[2][0] = fma2(p2, wA.x, d2[2][0]); d2[2][1] = fma2(p2, wA.y, d2[2][1]);
                d2[2][2] = fma2(p2, wB.x, d2[2][2]); d2[2][3] = fma2(p2, wB.y, d2[2][3]);
                d2[3][0] = fma2(p3, wA.x, d2[3][0]); d2[3][1] = fma2(p3, wA.y, d2[3][1]);
                d2[3][2] = fma2(p3, wB.x, d2[3][2]); d2[3][3] = fma2(p3, wB.y, d2[3][3]);
            }
        }
#pragma unroll
        for (int i = 0; i < 4; i++)
#pragma unroll
            for (int j = 0; j < 4; j++) {
                float blo, bhi, dlo, dhi;
                upk2(blo, bhi, base2[i][j]);
                upk2(dlo, dhi, d2[i][j]);
                sH1[(ty * 4 + i) * STX + tx * 8 + 2 * j]     = fmaxf(blo + dlo, 0.0f);
                sH1[(ty * 4 + i) * STX + tx * 8 + 2 * j + 1] = fmaxf(bhi + dhi, 0.0f);
            }
        __syncthreads();

        // ---- GEMM2 on tensor cores: h2 = relu(h1 @ W2 + b2), 3xTF32 ----
        {
            float acc[4][4];
#pragma unroll
            for (int j = 0; j < 4; j++) {
                int col0 = n0 + j * 8 + 2 * t4;
                acc[j][0] = sB2[col0];
                acc[j][1] = sB2[col0 + 1];
                acc[j][2] = acc[j][0];
                acc[j][3] = acc[j][1];
            }
#pragma unroll 2
            for (int s = 0; s < 16; s++) {
                int k0 = s * 8;
                // A fragment (h1), conflict-free
                float a0f = sH1[(m0 + g) * STX + k0 + t4];
                float a1f = sH1[(m0 + g + 8) * STX + k0 + t4];
                float a2f = sH1[(m0 + g) * STX + k0 + t4 + 4];
                float a3f = sH1[(m0 + g + 8) * STX + k0 + t4 + 4];
                float ab0 = tf32rna(a0f), ab1 = tf32rna(a1f);
                float ab2 = tf32rna(a2f), ab3 = tf32rna(a3f);
                float as0 = tf32rna(a0f - ab0), as1 = tf32rna(a1f - ab1);
                float as2 = tf32rna(a2f - ab2), as3 = tf32rna(a3f - ab3);
                uint32_t ub0 = __float_as_uint(ab0), ub1 = __float_as_uint(ab1);
                uint32_t ub2 = __float_as_uint(ab2), ub3 = __float_as_uint(ab3);
                uint32_t us0 = __float_as_uint(as0), us1 = __float_as_uint(as1);
                uint32_t us2 = __float_as_uint(as2), us3 = __float_as_uint(as3);
#pragma unroll
                for (int j = 0; j < 4; j++) {
                    int col = n0 + j * 8 + g;
                    uint32_t bb0 = __float_as_uint(W2bigT[col * 132 + k0 + t4]);
                    uint32_t bb1 = __float_as_uint(W2bigT[col * 132 + k0 + t4 + 4]);
                    uint32_t bs0 = __float_as_uint(W2smlT[col * 132 + k0 + t4]);
                    uint32_t bs1 = __float_as_uint(W2smlT[col * 132 + k0 + t4 + 4]);
                    mma_tf32(acc[j], ub0, ub1, ub2, ub3, bb0, bb1);
                    mma_tf32(acc[j], us0, us1, us2, us3, bb0, bb1);
                    mma_tf32(acc[j], ub0, ub1, ub2, ub3, bs0, bs1);
                }
            }
            // store relu(h2)
#pragma unroll
            for (int j = 0; j < 4; j++) {
                int col0 = n0 + j * 8 + 2 * t4;
                sH2[(m0 + g) * STH + col0]         = fmaxf(acc[j][0], 0.0f);
                sH2[(m0 + g) * STH + col0 + 1]     = fmaxf(acc[j][1], 0.0f);
                sH2[(m0 + g + 8) * STH + col0]     = fmaxf(acc[j][2], 0.0f);
                sH2[(m0 + g + 8) * STH + col0 + 1] = fmaxf(acc[j][3], 0.0f);
            }
        }
        __syncthreads();

        // GEMM3: p = h2 @ W3 + b3 ; accumulate (bit-frozen scalar)
        {
            int rr = tid >> 2;
            int cg = (tid & 3) * 4;
            u64t q0 = pk2(sB3[cg + 0], sB3[cg + 1]);
            u64t q1 = pk2(sB3[cg + 2], sB3[cg + 3]);
            for (int k4 = 0; k4 < 64; k4 += 4) {
                float4 av = *(const float4*)&sH2[rr * STH + k4];
#pragma unroll
                for (int kk = 0; kk < 4; kk++) {
                    ulonglong2 w = *(const ulonglong2*)&sW3[(k4 + kk) * 16 + cg];
                    float a = (&av.x)[kk];
                    u64t pa = pk2(a, a);
                    q0 = fma2(pa, w.x, q0);
                    q1 = fma2(pa, w.y, q1);
                }
            }
            float p0, p1, p2, p3;
            upk2(p0, p1, q0);
            upk2(p2, p3, q1);
            if (v == 0) {
                sPw[rr * 16 + cg + 0] = p0; sPw[rr * 16 + cg + 1] = p1;
                sPw[rr * 16 + cg + 2] = p2; sPw[rr * 16 + cg + 3] = p3;
            } else if (v == 1) {
                sPa[rr * 16 + cg + 0] = p0; sPa[rr * 16 + cg + 1] = p1;
                sPa[rr * 16 + cg + 2] = p2; sPa[rr * 16 + cg + 3] = p3;
            } else {
                sPa[rr * 16 + cg + 0] += p0;
                sPa[rr * 16 + cg + 1] += p1;
                sPa[rr * 16 + cg + 2] += p2;
                sPa[rr * 16 + cg + 3] += p3;
            }
        }
        __syncthreads();
    }

    // ---- epilogue: per-row KL in f64 ----
    if (tid < MT) {
        const int r = tid;
        const double INV11 = 1.0 / 11.0;
        double pw[16], po[16];
#pragma unroll
        for (int a = 0; a < 16; a++) {
            pw[a] = (double)sPw[r * 16 + a];
            po[a] = (double)sPa[r * 16 + a] * INV11;
        }
        double mw = pw[0], mo = po[0];
#pragma unroll
        for (int a = 1; a < 16; a++) {
            mw = fmax(mw, pw[a]);
            mo = fmax(mo, po[a]);
        }
        double eo[16];
        double sw = 0.0, so = 0.0;
#pragma unroll
        for (int a = 0; a < 16; a++) {
            sw += fexp(pw[a] - mw);
            eo[a] = fexp(po[a] - mo);
            so += eo[a];
        }
        double lsw = flog(sw);
        double lso = flog(so);
        double inv_so = 1.0 / so;
        double infl = 0.0;
#pragma unroll
        for (int a = 0; a < 16; a++) {
            double q = eo[a] * inv_so;
            double logq = (po[a] - mo) - lso;
            double logp = (pw[a] - mw) - lsw;
            infl += q * (logq - logp);
        }
        g_infl[row0 + r] = infl;
    }
}

// ---------------- finalize: mean over N, normalize over T (f64) ----------------
__global__ void finalize_kernel(float* __restrict__ out) {
    const int b = blockIdx.x;
    const int tid = threadIdx.x;
    __shared__ double v[512];
    __shared__ double red[256];
    for (int t = tid; t < 512; t += 256) {
        const double* p = &g_infl[((size_t)b * 512 + t) * 10];
        double s = 0.0;
#pragma unroll
        for (int n = 0; n < 10; n++) s += p[n];
        v[t] = s;
    }
    __syncthreads();
    red[tid] = v[tid] + v[tid + 256];
    __syncthreads();
    for (int o = 128; o > 0; o >>= 1) {
        if (tid < o) red[tid] += red[tid + o];
        __syncthreads();
    }
    double tot = red[0];
    for (int t = tid; t < 512; t += 256)
        out[(size_t)b * 512 + t] = (float)(v[t] / tot);
}

// ---------------- launch ----------------
extern "C" void kernel_launch(void* const* d_in, const int* in_sizes, int n_in,
                              void* d_out, int out_size) {
    const float* obs     = (const float*)d_in[0];
    const float* actions = (const float*)d_in[1];
    const float* W1      = (const float*)d_in[2];
    const float* b1      = (const float*)d_in[3];
    const float* W2      = (const float*)d_in[4];
    const float* b2      = (const float*)d_in[5];
    const float* W3      = (const float*)d_in[6];
    const float* b3      = (const float*)d_in[7];

    cudaFuncSetAttribute(fused_kernel, cudaFuncAttributeMaxDynamicSharedMemorySize,
                         (int)SMEM_BYTES);
    fused_kernel<<<NTILES, 256, SMEM_BYTES>>>(obs, actions, W1, b1, W2, b2, W3, b3);
    finalize_kernel<<<32, 256>>>((float*)d_out);
}

// round 15
// speedup vs baseline: 1.5571x; 1.2136x over previous
#include <cuda_runtime.h>
#include <cstdint>
#include <math.h>

// Numerics: GEMM1/delta/GEMM3 bit-frozen scalar fp32 chains. GEMM2 on tensor
// cores via mma.sync m16n8k8 with PLAIN TF32 operands (1x). Error budget:
// R3 measured that tf32-rounding ALL matmul operands adds 0.56e-3 (quadrature);
// GEMM2-only rounding is a subset => added noise <= 0.56e-3 => total
// <= sqrt(0.7004^2 + 0.56^2) = 0.896e-3 < 1e-3 (measured hard bound).
// PRNG: JAX partitionable threefry. Epilogue: fast f64.

// ---------------- problem constants ----------------
constexpr int NV = 12;
constexpr int R = 32 * 512 * 10;                      // 163840 rows
constexpr int MT = 64;
constexpr int NTILES = R / MT;                        // 2560
constexpr int STX = 132;
constexpr int STH = 68;

// ---------------- smem layout (floats) ----------------
constexpr int OFF_W1 = 0;                     // [144][128]
constexpr int OFF_W2 = OFF_W1 + 144 * 128;
constexpr int OFF_W3 = OFF_W2 + 128 * 64;
constexpr int OFF_B1 = OFF_W3 + 64 * 16;
constexpr int OFF_B2 = OFF_B1 + 128;
constexpr int OFF_B3 = OFF_B2 + 64;
constexpr int OFF_X  = OFF_B3 + 16;           // obs tile [64][132]; reused as W2bigT
constexpr int OFF_H1 = OFF_X + MT * STX;
constexpr int OFF_H2 = OFF_H1 + MT * STX;
constexpr int OFF_ACT = OFF_H2 + MT * STH;
constexpr int OFF_PW = OFF_ACT + MT * 16;
constexpr int OFF_PA = OFF_PW + MT * 16;
constexpr int SMEM_FLOATS = OFF_PA + MT * 16;
constexpr size_t SMEM_BYTES = SMEM_FLOATS * sizeof(float); // ~208 KB

__device__ double g_infl[R];

// ---------------- packed f32x2 helpers ----------------
typedef unsigned long long u64t;

__device__ __forceinline__ u64t pk2(float lo, float hi) {
    u64t d;
    asm("mov.b64 %0, {%1, %2};" : "=l"(d)
        : "r"(__float_as_uint(lo)), "r"(__float_as_uint(hi)));
    return d;
}
__device__ __forceinline__ void upk2(float& lo, float& hi, u64t s) {
    uint32_t a, b;
    asm("mov.b64 {%0, %1}, %2;" : "=r"(a), "=r"(b) : "l"(s));
    lo = __uint_as_float(a);
    hi = __uint_as_float(b);
}
__device__ __forceinline__ u64t fma2(u64t a, u64t b, u64t c) {
    u64t d;
    asm("fma.rn.f32x2 %0, %1, %2, %3;" : "=l"(d) : "l"(a), "l"(b), "l"(c));
    return d;
}

// ---------------- tf32 helpers ----------------
__device__ __forceinline__ uint32_t tf32bits(float x) {
    uint32_t u;
    asm("cvt.rna.tf32.f32 %0, %1;" : "=r"(u) : "f"(x));
    return u;
}

// mma.sync m16n8k8 tf32: d += a*b (f32 accumulate)
__device__ __forceinline__ void mma_tf32(float* d,
                                         uint32_t a0, uint32_t a1, uint32_t a2, uint32_t a3,
                                         uint32_t b0, uint32_t b1) {
    asm volatile(
        "mma.sync.aligned.m16n8k8.row.col.f32.tf32.tf32.f32 "
        "{%0,%1,%2,%3}, {%4,%5,%6,%7}, {%8,%9}, {%0,%1,%2,%3};"
        : "+f"(d[0]), "+f"(d[1]), "+f"(d[2]), "+f"(d[3])
        : "r"(a0), "r"(a1), "r"(a2), "r"(a3), "r"(b0), "r"(b1));
}

// ---------------- fast f64 exp/log (err ~1e-13, args bounded) ----------------
__device__ __forceinline__ double fexp(double x) {
    double n = floor(fma(x, 1.4426950408889634, 0.5));
    double r = fma(n, -6.93147180369123816490e-01, x);
    r = fma(n, -1.90821492927058770002e-10, r);
    double p = 2.5052108385441718775e-8;
    p = fma(p, r, 2.7557319223985890653e-7);
    p = fma(p, r, 2.7557319223985892511e-6);
    p = fma(p, r, 2.4801587301587301566e-5);
    p = fma(p, r, 1.9841269841269841253e-4);
    p = fma(p, r, 1.3888888888888889419e-3);
    p = fma(p, r, 8.3333333333333332177e-3);
    p = fma(p, r, 4.1666666666666664354e-2);
    p = fma(p, r, 1.6666666666666665741e-1);
    p = fma(p, r, 5.0e-1);
    p = fma(p, r, 1.0);
    p = fma(p, r, 1.0);
    int ni = (int)n;
    double two_n = __longlong_as_double((long long)(1023 + ni) << 52);
    return p * two_n;
}

__device__ __forceinline__ double flog(double x) {
    long long b = __double_as_longlong(x);
    int e = (int)(b >> 52) - 1022;
    double m = __longlong_as_double((b & 0x000FFFFFFFFFFFFFLL) | 0x3FE0000000000000LL);
    if (m < 0.70710678118654752440) { m = m + m; e -= 1; }
    double f = m - 1.0;
    double s = f / (f + 2.0);
    double z = s * s;
    double p = 0.15384615384615385469;
    p = fma(p, z, 0.18181818181818182323);
    p = fma(p, z, 0.22222222222222220989);
    p = fma(p, z, 0.28571428571428569843);
    p = fma(p, z, 0.40000000000000002220);
    p = fma(p, z, 0.66666666666666662966);
    p = fma(p, z, 2.0);
    double lm = s * p;
    return fma((double)e, 0.69314718055994530942, lm);
}

// ---------------- threefry2x32 (20 rounds, JAX-exact) ----------------
__device__ __forceinline__ void tf2x32(uint32_t k0, uint32_t k1,
                                       uint32_t c0, uint32_t c1,
                                       uint32_t& o0, uint32_t& o1) {
    uint32_t ks2 = k0 ^ k1 ^ 0x1BD11BDAu;
    uint32_t x0 = c0 + k0, x1 = c1 + k1;
#define TF_R(r) { x0 += x1; x1 = (x1 << (r)) | (x1 >> (32 - (r))); x1 ^= x0; }
    TF_R(13) TF_R(15) TF_R(26) TF_R(6)
    x0 += k1;  x1 += ks2 + 1u;
    TF_R(17) TF_R(29) TF_R(16) TF_R(24)
    x0 += ks2; x1 += k0 + 2u;
    TF_R(13) TF_R(15) TF_R(26) TF_R(6)
    x0 += k0;  x1 += k1 + 3u;
    TF_R(17) TF_R(29) TF_R(16) TF_R(24)
    x0 += k1;  x1 += ks2 + 4u;
    TF_R(13) TF_R(15) TF_R(26) TF_R(6)
    x0 += ks2; x1 += k0 + 5u;
#undef TF_R
    o0 = x0; o1 = x1;
}

__device__ __forceinline__ float u01(uint32_t bits) {
    return __uint_as_float((bits >> 9) | 0x3F800000u) - 1.0f;
}

// ---------------- fused kernel ----------------
__global__ __launch_bounds__(256, 1)
void fused_kernel(const float* __restrict__ obs, const float* __restrict__ actions,
                  const float* __restrict__ W1, const float* __restrict__ b1,
                  const float* __restrict__ W2, const float* __restrict__ b2,
                  const float* __restrict__ W3, const float* __restrict__ b3) {
    extern __shared__ float sm[];
    float* sW1 = sm + OFF_W1;
    float* sW2 = sm + OFF_W2;
    float* sW3 = sm + OFF_W3;
    float* sB1 = sm + OFF_B1;
    float* sB2 = sm + OFF_B2;
    float* sB3 = sm + OFF_B3;
    float* sX  = sm + OFF_X;
    float* sH1 = sm + OFF_H1;
    float* sH2 = sm + OFF_H2;
    float* sAct = sm + OFF_ACT;
    float* sPw = sm + OFF_PW;
    float* sPa = sm + OFF_PA;
    // post-GEMM1 reuse: tf32-rounded W2 transposed [col][k] stride 132
    float* W2bigT = sX;            // 64*132 = 8448 floats (obs dead after GEMM1)

    const int tid = threadIdx.x;

    {
        const float4* s; float4* d;
        s = (const float4*)W1; d = (float4*)sW1;
        for (int i = tid; i < 144 * 128 / 4; i += 256) d[i] = s[i];
        s = (const float4*)W2; d = (float4*)sW2;
        for (int i = tid; i < 128 * 64 / 4; i += 256) d[i] = s[i];
        s = (const float4*)W3; d = (float4*)sW3;
        for (int i = tid; i < 64 * 16 / 4; i += 256) d[i] = s[i];
        s = (const float4*)b1; d = (float4*)sB1;
        for (int i = tid; i < 32; i += 256) d[i] = s[i];
        s = (const float4*)b2; d = (float4*)sB2;
        if (tid < 16) d[tid] = s[tid];
        s = (const float4*)b3; d = (float4*)sB3;
        if (tid < 4) d[tid] = s[tid];
    }

    const int row0 = blockIdx.x * MT;

    for (int i = tid; i < MT * 32; i += 256) {
        int r = i >> 5, c4 = i & 31;
        float4 v = ((const float4*)obs)[(size_t)(row0 + r) * 32 + c4];
        *(float4*)&sX[r * STX + c4 * 4] = v;
    }
    __syncthreads();

    const int tx = tid & 15;
    const int ty = tid >> 4;
    const int wid = tid >> 5;
    const int lane = tid & 31;
    const int g = lane >> 2;      // mma group id
    const int t4 = lane & 3;      // mma thread-in-group

    // ---- GEMM1: base = obs @ W1[:128] + b1 ; kept in REGISTERS (bit-frozen) ----
    u64t base2[4][4];
    {
        u64t bp[4];
#pragma unroll
        for (int j = 0; j < 4; j++)
            bp[j] = pk2(sB1[tx * 8 + 2 * j], sB1[tx * 8 + 2 * j + 1]);
#pragma unroll
        for (int i = 0; i < 4; i++)
#pragma unroll
            for (int j = 0; j < 4; j++) base2[i][j] = bp[j];
    }

    for (int k4 = 0; k4 < 128; k4 += 4) {
        float4 A0 = *(const float4*)&sX[(ty * 4 + 0) * STX + k4];
        float4 A1 = *(const float4*)&sX[(ty * 4 + 1) * STX + k4];
        float4 A2 = *(const float4*)&sX[(ty * 4 + 2) * STX + k4];
        float4 A3 = *(const float4*)&sX[(ty * 4 + 3) * STX + k4];
#pragma unroll
        for (int kk = 0; kk < 4; kk++) {
            const ulonglong2* wp = (const ulonglong2*)&sW1[(k4 + kk) * 128 + tx * 8];
            ulonglong2 wA = wp[0], wB = wp[1];
            float a0 = (&A0.x)[kk], a1 = (&A1.x)[kk], a2 = (&A2.x)[kk], a3 = (&A3.x)[kk];
            u64t p0 = pk2(a0, a0), p1 = pk2(a1, a1), p2 = pk2(a2, a2), p3 = pk2(a3, a3);
            base2[0][0] = fma2(p0, wA.x, base2[0][0]); base2[0][1] = fma2(p0, wA.y, base2[0][1]);
            base2[0][2] = fma2(p0, wB.x, base2[0][2]); base2[0][3] = fma2(p0, wB.y, base2[0][3]);
            base2[1][0] = fma2(p1, wA.x, base2[1][0]); base2[1][1] = fma2(p1, wA.y, base2[1][1]);
            base2[1][2] = fma2(p1, wB.x, base2[1][2]); base2[1][3] = fma2(p1, wB.y, base2[1][3]);
            base2[2][0] = fma2(p2, wA.x, base2[2][0]); base2[2][1] = fma2(p2, wA.y, base2[2][1]);
            base2[2][2] = fma2(p2, wB.x, base2[2][2]); base2[2][3] = fma2(p2, wB.y, base2[2][3]);
            base2[3][0] = fma2(p3, wA.x, base2[3][0]); base2[3][1] = fma2(p3, wA.y, base2[3][1]);
            base2[3][2] = fma2(p3, wB.x, base2[3][2]); base2[3][3] = fma2(p3, wB.y, base2[3][3]);
        }
    }
    __syncthreads();   // everyone done reading sX (obs)

    // ---- tf32-round + transpose W2 -> W2bigT [col][k], stride 132 ----
    for (int idx = tid; idx < 128 * 64; idx += 256) {
        int k = idx >> 6, c = idx & 63;
        W2bigT[c * 132 + k] = __uint_as_float(tf32bits(sW2[k * 64 + c]));
    }
    __syncthreads();

    // mma tiling for GEMM2: warp -> rows m0..m0+15, cols n0..n0+31
    const int m0 = (wid & 3) * 16;
    const int n0 = (wid >> 2) * 32;

    // ---- variant loop ----
    for (int v = 0; v < NV; v++) {
        if (v == 0) {
            for (int i = tid; i < MT * 16 / 4; i += 256)
                ((float4*)sAct)[i] = ((const float4*)actions)[(size_t)row0 * 4 + i];
        } else if (v == 1) {
            for (int i = tid; i < MT * 16; i += 256) sAct[i] = 0.0f;
        } else {
            uint32_t s = (uint32_t)(v - 2);
            uint32_t k0, k1;
            tf2x32(0u, 1u, 0u, s, k0, k1);
            for (int i = tid; i < MT * 16; i += 256) {
                uint32_t gi = (uint32_t)row0 * 16u + (uint32_t)i;
                uint32_t o0, o1;
                tf2x32(k0, k1, 0u, gi, o0, o1);
                sAct[i] = u01(o0 ^ o1);
            }
        }
        __syncthreads();

        // delta = act @ W1[128:144]; h1 = relu(base + delta) -> sH1 (bit-frozen)
        u64t d2[4][4];
#pragma unroll
        for (int i = 0; i < 4; i++)
#pragma unroll
            for (int j = 0; j < 4; j++) d2[i][j] = 0ull;
#pragma unroll
        for (int k4 = 0; k4 < 16; k4 += 4) {
            float4 A0 = *(const float4*)&sAct[(ty * 4 + 0) * 16 + k4];
            float4 A1 = *(const float4*)&sAct[(ty * 4 + 1) * 16 + k4];
            float4 A2 = *(const float4*)&sAct[(ty * 4 + 2) * 16 + k4];
            float4 A3 = *(const float4*)&sAct[(ty * 4 + 3) * 16 + k4];
#pragma unroll
            for (int kk = 0; kk < 4; kk++) {
                const ulonglong2* wp = (const ulonglong2*)&sW1[(128 + k4 + kk) * 128 + tx * 8];
                ulonglong2 wA = wp[0], wB = wp[1];
                float a0 = (&A0.x)[kk], a1 = (&A1.x)[kk], a2 = (&A2.x)[kk], a3 = (&A3.x)[kk];
                u64t p0 = pk2(a0, a0), p1 = pk2(a1, a1), p2 = pk2(a2, a2), p3 = pk2(a3, a3);
                d2[0][0] = fma2(p0, wA.x, d2[0][0]); d2[0][1] = fma2(p0, wA.y, d2[0][1]);
                d2[0][2] = fma2(p0, wB.x, d2[0][2]); d2[0][3] = fma2(p0, wB.y, d2[0][3]);
                d2[1][0] = fma2(p1, wA.x, d2[1][0]); d2[1][1] = fma2(p1, wA.y, d2[1][1]);
                d2[1][2] = fma2(p1, wB.x, d2[1][2]); d2[1][3] = fma2(p1, wB.y, d2[1][3]);
                d2[2][0] = fma2(p2, wA.x, d2[2][0]); d2[2][1] = fma2(p2, wA.y, d2[2][1]);
                d2[2][2] = fma2(p2, wB.x, d2[2][2]); d2[2][3] = fma2(p2, wB.y, d2[2][3]);
                d2[3][0] = fma2(p3, wA.x, d2[3][0]); d2[3][1] = fma2(p3, wA.y, d2[3][1]);
                d2[3][2] = fma2(p3, wB.x, d2[3][2]); d2[3][3] = fma2(p3, wB.y, d2[3][3]);
            }
        }
#pragma unroll
        for (int i = 0; i < 4; i++)
#pragma unroll
            for (int j = 0; j < 4; j++) {
                float blo, bhi, dlo, dhi;
                upk2(blo, bhi, base2[i][j]);
                upk2(dlo, dhi, d2[i][j]);
                sH1[(ty * 4 + i) * STX + tx * 8 + 2 * j]     = fmaxf(blo + dlo, 0.0f);
                sH1[(ty * 4 + i) * STX + tx * 8 + 2 * j + 1] = fmaxf(bhi + dhi, 0.0f);
            }
        __syncthreads();

        // ---- GEMM2 on tensor cores: h2 = relu(h1 @ W2 + b2), 1xTF32 ----
        {
            float acc[4][4];
#pragma unroll
            for (int j = 0; j < 4; j++) {
                int col0 = n0 + j * 8 + 2 * t4;
                acc[j][0] = sB2[col0];
                acc[j][1] = sB2[col0 + 1];
                acc[j][2] = acc[j][0];
                acc[j][3] = acc[j][1];
            }
#pragma unroll 4
            for (int s = 0; s < 16; s++) {
                int k0 = s * 8;
                uint32_t ua0 = tf32bits(sH1[(m0 + g) * STX + k0 + t4]);
                uint32_t ua1 = tf32bits(sH1[(m0 + g + 8) * STX + k0 + t4]);
                uint32_t ua2 = tf32bits(sH1[(m0 + g) * STX + k0 + t4 + 4]);
                uint32_t ua3 = tf32bits(sH1[(m0 + g + 8) * STX + k0 + t4 + 4]);
#pragma unroll
                for (int j = 0; j < 4; j++) {
                    int col = n0 + j * 8 + g;
                    uint32_t bb0 = __float_as_uint(W2bigT[col * 132 + k0 + t4]);
                    uint32_t bb1 = __float_as_uint(W2bigT[col * 132 + k0 + t4 + 4]);
                    mma_tf32(acc[j], ua0, ua1, ua2, ua3, bb0, bb1);
                }
            }
            // store relu(h2)
#pragma unroll
            for (int j = 0; j < 4; j++) {
                int col0 = n0 + j * 8 + 2 * t4;
                sH2[(m0 + g) * STH + col0]         = fmaxf(acc[j][0], 0.0f);
                sH2[(m0 + g) * STH + col0 + 1]     = fmaxf(acc[j][1], 0.0f);
                sH2[(m0 + g + 8) * STH + col0]     = fmaxf(acc[j][2], 0.0f);
                sH2[(m0 + g + 8) * STH + col0 + 1] = fmaxf(acc[j][3], 0.0f);
            }
        }
        __syncthreads();

        // GEMM3: p = h2 @ W3 + b3 ; accumulate (bit-frozen scalar)
        {
            int rr = tid >> 2;
            int cg = (tid & 3) * 4;
            u64t q0 = pk2(sB3[cg + 0], sB3[cg + 1]);
            u64t q1 = pk2(sB3[cg + 2], sB3[cg + 3]);
            for (int k4 = 0; k4 < 64; k4 += 4) {
                float4 av = *(const float4*)&sH2[rr * STH + k4];
#pragma unroll
                for (int kk = 0; kk < 4; kk++) {
                    ulonglong2 w = *(const ulonglong2*)&sW3[(k4 + kk) * 16 + cg];
                    float a = (&av.x)[kk];
                    u64t pa = pk2(a, a);
                    q0 = fma2(pa, w.x, q0);
                    q1 = fma2(pa, w.y, q1);
                }
            }
            float p0, p1, p2, p3;
            upk2(p0, p1, q0);
            upk2(p2, p3, q1);
            if (v == 0) {
                sPw[rr * 16 + cg + 0] = p0; sPw[rr * 16 + cg + 1] = p1;
                sPw[rr * 16 + cg + 2] = p2; sPw[rr * 16 + cg + 3] = p3;
            } else if (v == 1) {
                sPa[rr * 16 + cg + 0] = p0; sPa[rr * 16 + cg + 1] = p1;
                sPa[rr * 16 + cg + 2] = p2; sPa[rr * 16 + cg + 3] = p3;
            } else {
                sPa[rr * 16 + cg + 0] += p0;
                sPa[rr * 16 + cg + 1] += p1;
                sPa[rr * 16 + cg + 2] += p2;
                sPa[rr * 16 + cg + 3] += p3;
            }
        }
        __syncthreads();
    }

    // ---- epilogue: per-row KL in f64 ----
    if (tid < MT) {
        const int r = tid;
        const double INV11 = 1.0 / 11.0;
        double pw[16], po[16];
#pragma unroll
        for (int a = 0; a < 16; a++) {
            pw[a] = (double)sPw[r * 16 + a];
            po[a] = (double)sPa[r * 16 + a] * INV11;
        }
        double mw = pw[0], mo = po[0];
#pragma unroll
        for (int a = 1; a < 16; a++) {
            mw = fmax(mw, pw[a]);
            mo = fmax(mo, po[a]);
        }
        double eo[16];
        double sw = 0.0, so = 0.0;
#pragma unroll
        for (int a = 0; a < 16; a++) {
            sw += fexp(pw[a] - mw);
            eo[a] = fexp(po[a] - mo);
            so += eo[a];
        }
        double lsw = flog(sw);
        double lso = flog(so);
        double inv_so = 1.0 / so;
        double infl = 0.0;
#pragma unroll
        for (int a = 0; a < 16; a++) {
            double q = eo[a] * inv_so;
            double logq = (po[a] - mo) - lso;
            double logp = (pw[a] - mw) - lsw;
            infl += q * (logq - logp);
        }
        g_infl[row0 + r] = infl;
    }
}

// ---------------- finalize: mean over N, normalize over T (f64) ----------------
__global__ void finalize_kernel(float* __restrict__ out) {
    const int b = blockIdx.x;
    const int tid = threadIdx.x;
    __shared__ double v[512];
    __shared__ double red[256];
    for (int t = tid; t < 512; t += 256) {
        const double* p = &g_infl[((size_t)b * 512 + t) * 10];
        double s = 0.0;
#pragma unroll
        for (int n = 0; n < 10; n++) s += p[n];
        v[t] = s;
    }
    __syncthreads();
    red[tid] = v[tid] + v[tid + 256];
    __syncthreads();
    for (int o = 128; o > 0; o >>= 1) {
        if (tid < o) red[tid] += red[tid + o];
        __syncthreads();
    }
    double tot = red[0];
    for (int t = tid; t < 512; t += 256)
        out[(size_t)b * 512 + t] = (float)(v[t] / tot);
}

// ---------------- launch ----------------
extern "C" void kernel_launch(void* const* d_in, const int* in_sizes, int n_in,
                              void* d_out, int out_size) {
    const float* obs     = (const float*)d_in[0];
    const float* actions = (const float*)d_in[1];
    const float* W1      = (const float*)d_in[2];
    const float* b1      = (const float*)d_in[3];
    const float* W2      = (const float*)d_in[4];
    const float* b2      = (const float*)d_in[5];
    const float* W3      = (const float*)d_in[6];
    const float* b3      = (const float*)d_in[7];

    cudaFuncSetAttribute(fused_kernel, cudaFuncAttributeMaxDynamicSharedMemorySize,
                         (int)SMEM_BYTES);
    fused_kernel<<<NTILES, 256, SMEM_BYTES>>>(obs, actions, W1, b1, W2, b2, W3, b3);
    finalize_kernel<<<32, 256>>>((float*)d_out);
}

// round 16
// speedup vs baseline: 1.8498x; 1.1880x over previous
#include <cuda_runtime.h>
#include <cstdint>
#include <math.h>

// Numerics: GEMM1 bit-frozen scalar fp32. delta & GEMM3 on tensor cores with
// 3xTF32 (measured equivalent to fp32: R14 delta-rel_err ~3e-9). GEMM2 on
// tensor cores 1xTF32 (measured added noise 0.474e-3; total 0.8456e-3 < 1e-3).
// PRNG: JAX partitionable threefry. Epilogue: fast f64.

// ---------------- problem constants ----------------
constexpr int NV = 12;
constexpr int R = 32 * 512 * 10;                      // 163840 rows
constexpr int MT = 64;
constexpr int NTILES = R / MT;                        // 2560
constexpr int STX = 132;
constexpr int STH = 68;
constexpr int STA = 20;                               // sAct stride (conflict-free)

// ---------------- smem layout (floats) ----------------
constexpr int OFF_W1 = 0;                     // [144][128]; rows 0-127 reused post-GEMM1
constexpr int OFF_W2 = OFF_W1 + 144 * 128;
constexpr int OFF_W3 = OFF_W2 + 128 * 64;
constexpr int OFF_B1 = OFF_W3 + 64 * 16;
constexpr int OFF_B2 = OFF_B1 + 128;
constexpr int OFF_B3 = OFF_B2 + 64;
constexpr int OFF_X  = OFF_B3 + 16;           // obs tile [64][132]; reused as W2bigT
constexpr int OFF_H1 = OFF_X + MT * STX;
constexpr int OFF_H2 = OFF_H1 + MT * STX;
constexpr int OFF_ACT = OFF_H2 + MT * STH;    // [64][20]
constexpr int OFF_PW = OFF_ACT + MT * STA;
constexpr int OFF_PA = OFF_PW + MT * 16;
constexpr int SMEM_FLOATS = OFF_PA + MT * 16;
constexpr size_t SMEM_BYTES = SMEM_FLOATS * sizeof(float); // ~210 KB

// reuse offsets inside dead W1 rows 0..127 region (16384 floats)
constexpr int ROFF_BASE  = 0;        // [64][132] = 8448
constexpr int ROFF_W1DB  = 8448;     // [128][20] = 2560
constexpr int ROFF_W1DS  = 11008;    // [128][20] = 2560
constexpr int ROFF_W3B   = 13568;    // [16][68]  = 1088
constexpr int ROFF_W3S   = 14656;    // [16][68]  = 1088  (ends 15744 < 16384)

__device__ double g_infl[R];

// ---------------- packed f32x2 helpers ----------------
typedef unsigned long long u64t;

__device__ __forceinline__ u64t pk2(float lo, float hi) {
    u64t d;
    asm("mov.b64 %0, {%1, %2};" : "=l"(d)
        : "r"(__float_as_uint(lo)), "r"(__float_as_uint(hi)));
    return d;
}
__device__ __forceinline__ void upk2(float& lo, float& hi, u64t s) {
    uint32_t a, b;
    asm("mov.b64 {%0, %1}, %2;" : "=r"(a), "=r"(b) : "l"(s));
    lo = __uint_as_float(a);
    hi = __uint_as_float(b);
}
__device__ __forceinline__ u64t fma2(u64t a, u64t b, u64t c) {
    u64t d;
    asm("fma.rn.f32x2 %0, %1, %2, %3;" : "=l"(d) : "l"(a), "l"(b), "l"(c));
    return d;
}

// ---------------- tf32 helpers ----------------
__device__ __forceinline__ uint32_t tf32bits(float x) {
    uint32_t u;
    asm("cvt.rna.tf32.f32 %0, %1;" : "=r"(u) : "f"(x));
    return u;
}

// mma.sync m16n8k8 tf32: d += a*b (f32 accumulate)
__device__ __forceinline__ void mma_tf32(float* d,
                                         uint32_t a0, uint32_t a1, uint32_t a2, uint32_t a3,
                                         uint32_t b0, uint32_t b1) {
    asm volatile(
        "mma.sync.aligned.m16n8k8.row.col.f32.tf32.tf32.f32 "
        "{%0,%1,%2,%3}, {%4,%5,%6,%7}, {%8,%9}, {%0,%1,%2,%3};"
        : "+f"(d[0]), "+f"(d[1]), "+f"(d[2]), "+f"(d[3])
        : "r"(a0), "r"(a1), "r"(a2), "r"(a3), "r"(b0), "r"(b1));
}

// ---------------- fast f64 exp/log (err ~1e-13, args bounded) ----------------
__device__ __forceinline__ double fexp(double x) {
    double n = floor(fma(x, 1.4426950408889634, 0.5));
    double r = fma(n, -6.93147180369123816490e-01, x);
    r = fma(n, -1.90821492927058770002e-10, r);
    double p = 2.5052108385441718775e-8;
    p = fma(p, r, 2.7557319223985890653e-7);
    p = fma(p, r, 2.7557319223985892511e-6);
    p = fma(p, r, 2.4801587301587301566e-5);
    p = fma(p, r, 1.9841269841269841253e-4);
    p = fma(p, r, 1.3888888888888889419e-3);
    p = fma(p, r, 8.3333333333333332177e-3);
    p = fma(p, r, 4.1666666666666664354e-2);
    p = fma(p, r, 1.6666666666666665741e-1);
    p = fma(p, r, 5.0e-1);
    p = fma(p, r, 1.0);
    p = fma(p, r, 1.0);
    int ni = (int)n;
    double two_n = __longlong_as_double((long long)(1023 + ni) << 52);
    return p * two_n;
}

__device__ __forceinline__ double flog(double x) {
    long long b = __double_as_longlong(x);
    int e = (int)(b >> 52) - 1022;
    double m = __longlong_as_double((b & 0x000FFFFFFFFFFFFFLL) | 0x3FE0000000000000LL);
    if (m < 0.70710678118654752440) { m = m + m; e -= 1; }
    double f = m - 1.0;
    double s = f / (f + 2.0);
    double z = s * s;
    double p = 0.15384615384615385469;
    p = fma(p, z, 0.18181818181818182323);
    p = fma(p, z, 0.22222222222222220989);
    p = fma(p, z, 0.28571428571428569843);
    p = fma(p, z, 0.40000000000000002220);
    p = fma(p, z, 0.66666666666666662966);
    p = fma(p, z, 2.0);
    double lm = s * p;
    return fma((double)e, 0.69314718055994530942, lm);
}

// ---------------- threefry2x32 (20 rounds, JAX-exact) ----------------
__device__ __forceinline__ void tf2x32(uint32_t k0, uint32_t k1,
                                       uint32_t c0, uint32_t c1,
                                       uint32_t& o0, uint32_t& o1) {
    uint32_t ks2 = k0 ^ k1 ^ 0x1BD11BDAu;
    uint32_t x0 = c0 + k0, x1 = c1 + k1;
#define TF_R(r) { x0 += x1; x1 = (x1 << (r)) | (x1 >> (32 - (r))); x1 ^= x0; }
    TF_R(13) TF_R(15) TF_R(26) TF_R(6)
    x0 += k1;  x1 += ks2 + 1u;
    TF_R(17) TF_R(29) TF_R(16) TF_R(24)
    x0 += ks2; x1 += k0 + 2u;
    TF_R(13) TF_R(15) TF_R(26) TF_R(6)
    x0 += k0;  x1 += k1 + 3u;
    TF_R(17) TF_R(29) TF_R(16) TF_R(24)
    x0 += k1;  x1 += ks2 + 4u;
    TF_R(13) TF_R(15) TF_R(26) TF_R(6)
    x0 += ks2; x1 += k0 + 5u;
#undef TF_R
    o0 = x0; o1 = x1;
}

__device__ __forceinline__ float u01(uint32_t bits) {
    return __uint_as_float((bits >> 9) | 0x3F800000u) - 1.0f;
}

// ---------------- fused kernel ----------------
__global__ __launch_bounds__(256, 1)
void fused_kernel(const float* __restrict__ obs, const float* __restrict__ actions,
                  const float* __restrict__ W1, const float* __restrict__ b1,
                  const float* __restrict__ W2, const float* __restrict__ b2,
                  const float* __restrict__ W3, const float* __restrict__ b3) {
    extern __shared__ float sm[];
    float* sW1 = sm + OFF_W1;
    float* sW2 = sm + OFF_W2;
    float* sW3 = sm + OFF_W3;
    float* sB1 = sm + OFF_B1;
    float* sB2 = sm + OFF_B2;
    float* sB3 = sm + OFF_B3;
    float* sX  = sm + OFF_X;
    float* sH1 = sm + OFF_H1;
    float* sH2 = sm + OFF_H2;
    float* sAct = sm + OFF_ACT;
    float* sPw = sm + OFF_PW;
    float* sPa = sm + OFF_PA;
    // post-GEMM1 reuse
    float* W2bigT = sX;                    // tf32 W2^T [col][k], stride 132
    float* sBase  = sW1 + ROFF_BASE;       // h1_base [64][132]
    float* W1dBig = sW1 + ROFF_W1DB;       // W1[128:144]^T big [col][k] stride 20
    float* W1dSml = sW1 + ROFF_W1DS;
    float* W3Big  = sW1 + ROFF_W3B;        // W3^T big [col][k] stride 68
    float* W3Sml  = sW1 + ROFF_W3S;

    const int tid = threadIdx.x;

    {
        const float4* s; float4* d;
        s = (const float4*)W1; d = (float4*)sW1;
        for (int i = tid; i < 144 * 128 / 4; i += 256) d[i] = s[i];
        s = (const float4*)W2; d = (float4*)sW2;
        for (int i = tid; i < 128 * 64 / 4; i += 256) d[i] = s[i];
        s = (const float4*)W3; d = (float4*)sW3;
        for (int i = tid; i < 64 * 16 / 4; i += 256) d[i] = s[i];
        s = (const float4*)b1; d = (float4*)sB1;
        for (int i = tid; i < 32; i += 256) d[i] = s[i];
        s = (const float4*)b2; d = (float4*)sB2;
        if (tid < 16) d[tid] = s[tid];
        s = (const float4*)b3; d = (float4*)sB3;
        if (tid < 4) d[tid] = s[tid];
    }

    const int row0 = blockIdx.x * MT;

    for (int i = tid; i < MT * 32; i += 256) {
        int r = i >> 5, c4 = i & 31;
        float4 v = ((const float4*)obs)[(size_t)(row0 + r) * 32 + c4];
        *(float4*)&sX[r * STX + c4 * 4] = v;
    }
    __syncthreads();

    const int tx = tid & 15;
    const int ty = tid >> 4;
    const int wid = tid >> 5;
    const int lane = tid & 31;
    const int g = lane >> 2;      // mma group id
    const int t4 = lane & 3;      // mma thread-in-group

    // ---- GEMM1: base = obs @ W1[:128] + b1 (bit-frozen scalar) ----
    u64t base2[4][4];
    {
        u64t bp[4];
#pragma unroll
        for (int j = 0; j < 4; j++)
            bp[j] = pk2(sB1[tx * 8 + 2 * j], sB1[tx * 8 + 2 * j + 1]);
#pragma unroll
        for (int i = 0; i < 4; i++)
#pragma unroll
            for (int j = 0; j < 4; j++) base2[i][j] = bp[j];
    }

    for (int k4 = 0; k4 < 128; k4 += 4) {
        float4 A0 = *(const float4*)&sX[(ty * 4 + 0) * STX + k4];
        float4 A1 = *(const float4*)&sX[(ty * 4 + 1) * STX + k4];
        float4 A2 = *(const float4*)&sX[(ty * 4 + 2) * STX + k4];
        float4 A3 = *(const float4*)&sX[(ty * 4 + 3) * STX + k4];
#pragma unroll
        for (int kk = 0; kk < 4; kk++) {
            const ulonglong2* wp = (const ulonglong2*)&sW1[(k4 + kk) * 128 + tx * 8];
            ulonglong2 wA = wp[0], wB = wp[1];
            float a0 = (&A0.x)[kk], a1 = (&A1.x)[kk], a2 = (&A2.x)[kk], a3 = (&A3.x)[kk];
            u64t p0 = pk2(a0, a0), p1 = pk2(a1, a1), p2 = pk2(a2, a2), p3 = pk2(a3, a3);
            base2[0][0] = fma2(p0, wA.x, base2[0][0]); base2[0][1] = fma2(p0, wA.y, base2[0][1]);
            base2[0][2] = fma2(p0, wB.x, base2[0][2]); base2[0][3] = fma2(p0, wB.y, base2[0][3]);
            base2[1][0] = fma2(p1, wA.x, base2[1][0]); base2[1][1] = fma2(p1, wA.y, base2[1][1]);
            base2[1][2] = fma2(p1, wB.x, base2[1][2]); base2[1][3] = fma2(p1, wB.y, base2[1][3]);
            base2[2][0] = fma2(p2, wA.x, base2[2][0]); base2[2][1] = fma2(p2, wA.y, base2[2][1]);
            base2[2][2] = fma2(p2, wB.x, base2[2][2]); base2[2][3] = fma2(p2, wB.y, base2[2][3]);
            base2[3][0] = fma2(p3, wA.x, base2[3][0]); base2[3][1] = fma2(p3, wA.y, base2[3][1]);
            base2[3][2] = fma2(p3, wB.x, base2[3][2]); base2[3][3] = fma2(p3, wB.y, base2[3][3]);
        }
    }
    __syncthreads();   // all reads of sX (obs) and sW1 rows 0-127 complete

    // ---- one-time prep: base -> smem; tf32 transposes of W2, W1delta, W3 ----
#pragma unroll
    for (int i = 0; i < 4; i++)
#pragma unroll
        for (int j = 0; j < 4; j++) {
            float lo, hi;
            upk2(lo, hi, base2[i][j]);
            sBase[(ty * 4 + i) * STX + tx * 8 + 2 * j]     = lo;
            sBase[(ty * 4 + i) * STX + tx * 8 + 2 * j + 1] = hi;
        }
    for (int idx = tid; idx < 128 * 64; idx += 256) {
        int k = idx >> 6, c = idx & 63;
        W2bigT[c * 132 + k] = __uint_as_float(tf32bits(sW2[k * 64 + c]));
    }
    for (int idx = tid; idx < 128 * 16; idx += 256) {
        int col = idx >> 4, k = idx & 15;
        float w = sW1[(128 + k) * 128 + col];
        float big = __uint_as_float(tf32bits(w));
        W1dBig[col * STA + k] = big;
        W1dSml[col * STA + k] = __uint_as_float(tf32bits(w - big));
    }
    for (int idx = tid; idx < 16 * 64; idx += 256) {
        int col = idx >> 6, k = idx & 63;
        float w = sW3[k * 16 + col];
        float big = __uint_as_float(tf32bits(w));
        W3Big[col * STH + k] = big;
        W3Sml[col * STH + k] = __uint_as_float(tf32bits(w - big));
    }
    __syncthreads();

    // warp tilings
    const int m0 = (wid & 3) * 16;       // shared m-tile for delta/GEMM2/GEMM3
    const int n0g2 = (wid >> 2) * 32;    // GEMM2 n-range (64 cols / 2)
    const int nbd = (wid >> 2) * 64;     // delta n-range (128 cols / 2)
    const int nt3 = (wid >> 2);          // GEMM3 n-tile (16 cols / 2)

    // GEMM3 accumulators (C-fragment registers, persist across variants)
    float accW3[4], accA3[4];

    // ---- variant loop ----
    for (int v = 0; v < NV; v++) {
        if (v == 0) {
            for (int i = tid; i < MT * 4; i += 256) {
                int r = i >> 2, c4 = i & 3;
                *(float4*)&sAct[r * STA + c4 * 4] =
                    ((const float4*)actions)[(size_t)row0 * 4 + i];
            }
        } else if (v == 1) {
            for (int i = tid; i < MT * STA; i += 256) sAct[i] = 0.0f;
        } else {
            uint32_t s = (uint32_t)(v - 2);
            uint32_t k0, k1;
            tf2x32(0u, 1u, 0u, s, k0, k1);   // key_s = threefry(key(1), (0,s))
            for (int i = tid; i < MT * 16; i += 256) {
                uint32_t gi = (uint32_t)row0 * 16u + (uint32_t)i;
                uint32_t o0, o1;
                tf2x32(k0, k1, 0u, gi, o0, o1);
                sAct[(i >> 4) * STA + (i & 15)] = u01(o0 ^ o1);
            }
        }
        __syncthreads();

        // ---- delta on tensor cores (3xTF32): h1 = relu(base + act@W1d) ----
        {
            uint32_t Ab[2][4], As[2][4];
#pragma unroll
            for (int s = 0; s < 2; s++) {
                int k0 = s * 8;
                float a0 = sAct[(m0 + g) * STA + k0 + t4];
                float a1 = sAct[(m0 + g + 8) * STA + k0 + t4];
                float a2 = sAct[(m0 + g) * STA + k0 + t4 + 4];
                float a3 = sAct[(m0 + g + 8) * STA + k0 + t4 + 4];
                Ab[s][0] = tf32bits(a0); As[s][0] = tf32bits(a0 - __uint_as_float(Ab[s][0]));
                Ab[s][1] = tf32bits(a1); As[s][1] = tf32bits(a1 - __uint_as_float(Ab[s][1]));
                Ab[s][2] = tf32bits(a2); As[s][2] = tf32bits(a2 - __uint_as_float(Ab[s][2]));
                Ab[s][3] = tf32bits(a3); As[s][3] = tf32bits(a3 - __uint_as_float(Ab[s][3]));
            }
#pragma unroll
            for (int j = 0; j < 8; j++) {
                int cj = nbd + j * 8;
                float acc[4];
                acc[0] = sBase[(m0 + g) * STX + cj + 2 * t4];
                acc[1] = sBase[(m0 + g) * STX + cj + 2 * t4 + 1];
                acc[2] = sBase[(m0 + g + 8) * STX + cj + 2 * t4];
                acc[3] = sBase[(m0 + g + 8) * STX + cj + 2 * t4 + 1];
                int colb = cj + g;
#pragma unroll
                for (int s = 0; s < 2; s++) {
                    int k0 = s * 8;
                    uint32_t bb0 = __float_as_uint(W1dBig[colb * STA + k0 + t4]);
                    uint32_t bb1 = __float_as_uint(W1dBig[colb * STA + k0 + t4 + 4]);
                    uint32_t bs0 = __float_as_uint(W1dSml[colb * STA + k0 + t4]);
                    uint32_t bs1 = __float_as_uint(W1dSml[colb * STA + k0 + t4 + 4]);
                    mma_tf32(acc, Ab[s][0], Ab[s][1], Ab[s][2], Ab[s][3], bb0, bb1);
                    mma_tf32(acc, As[s][0], As[s][1], As[s][2], As[s][3], bb0, bb1);
                    mma_tf32(acc, Ab[s][0], Ab[s][1], Ab[s][2], Ab[s][3], bs0, bs1);
                }
                sH1[(m0 + g) * STX + cj + 2 * t4]         = fmaxf(acc[0], 0.0f);
                sH1[(m0 + g) * STX + cj + 2 * t4 + 1]     = fmaxf(acc[1], 0.0f);
                sH1[(m0 + g + 8) * STX + cj + 2 * t4]     = fmaxf(acc[2], 0.0f);
                sH1[(m0 + g + 8) * STX + cj + 2 * t4 + 1] = fmaxf(acc[3], 0.0f);
            }
        }
        __syncthreads();

        // ---- GEMM2 on tensor cores: h2 = relu(h1 @ W2 + b2), 1xTF32 ----
        {
            float acc[4][4];
#pragma unroll
            for (int j = 0; j < 4; j++) {
                int col0 = n0g2 + j * 8 + 2 * t4;
                acc[j][0] = sB2[col0];
                acc[j][1] = sB2[col0 + 1];
                acc[j][2] = acc[j][0];
                acc[j][3] = acc[j][1];
            }
#pragma unroll 4
            for (int s = 0; s < 16; s++) {
                int k0 = s * 8;
                uint32_t ua0 = tf32bits(sH1[(m0 + g) * STX + k0 + t4]);
                uint32_t ua1 = tf32bits(sH1[(m0 + g + 8) * STX + k0 + t4]);
                uint32_t ua2 = tf32bits(sH1[(m0 + g) * STX + k0 + t4 + 4]);
                uint32_t ua3 = tf32bits(sH1[(m0 + g + 8) * STX + k0 + t4 + 4]);
#pragma unroll
                for (int j = 0; j < 4; j++) {
                    int col = n0g2 + j * 8 + g;
                    uint32_t bb0 = __float_as_uint(W2bigT[col * 132 + k0 + t4]);
                    uint32_t bb1 = __float_as_uint(W2bigT[col * 132 + k0 + t4 + 4]);
                    mma_tf32(acc[j], ua0, ua1, ua2, ua3, bb0, bb1);
                }
            }
#pragma unroll
            for (int j = 0; j < 4; j++) {
                int col0 = n0g2 + j * 8 + 2 * t4;
                sH2[(m0 + g) * STH + col0]         = fmaxf(acc[j][0], 0.0f);
                sH2[(m0 + g) * STH + col0 + 1]     = fmaxf(acc[j][1], 0.0f);
                sH2[(m0 + g + 8) * STH + col0]     = fmaxf(acc[j][2], 0.0f);
                sH2[(m0 + g + 8) * STH + col0 + 1] = fmaxf(acc[j][3], 0.0f);
            }
        }
        __syncthreads();

        // ---- GEMM3 on tensor cores (3xTF32): p = h2 @ W3 + b3, reg accumulate ----
        {
            float acc[4];
            int c0 = nt3 * 8 + 2 * t4;
            acc[0] = sB3[c0];
            acc[1] = sB3[c0 + 1];
            acc[2] = acc[0];
            acc[3] = acc[1];
            int colb = nt3 * 8 + g;
#pragma unroll
            for (int s = 0; s < 8; s++) {
                int k0 = s * 8;
                float a0 = sH2[(m0 + g) * STH + k0 + t4];
                float a1 = sH2[(m0 + g + 8) * STH + k0 + t4];
                float a2 = sH2[(m0 + g) * STH + k0 + t4 + 4];
                float a3 = sH2[(m0 + g + 8) * STH + k0 + t4 + 4];
                uint32_t ab0 = tf32bits(a0), as0 = tf32bits(a0 - __uint_as_float(ab0));
                uint32_t ab1 = tf32bits(a1), as1 = tf32bits(a1 - __uint_as_float(ab1));
                uint32_t ab2 = tf32bits(a2), as2 = tf32bits(a2 - __uint_as_float(ab2));
                uint32_t ab3 = tf32bits(a3), as3 = tf32bits(a3 - __uint_as_float(ab3));
                uint32_t bb0 = __float_as_uint(W3Big[colb * STH + k0 + t4]);
                uint32_t bb1 = __float_as_uint(W3Big[colb * STH + k0 + t4 + 4]);
                uint32_t bs0 = __float_as_uint(W3Sml[colb * STH + k0 + t4]);
                uint32_t bs1 = __float_as_uint(W3Sml[colb * STH + k0 + t4 + 4]);
                mma_tf32(acc, ab0, ab1, ab2, ab3, bb0, bb1);
                mma_tf32(acc, as0, as1, as2, as3, bb0, bb1);
                mma_tf32(acc, ab0, ab1, ab2, ab3, bs0, bs1);
            }
            if (v == 0) {
                accW3[0] = acc[0]; accW3[1] = acc[1]; accW3[2] = acc[2]; accW3[3] = acc[3];
            } else if (v == 1) {
                accA3[0] = acc[0]; accA3[1] = acc[1]; accA3[2] = acc[2]; accA3[3] = acc[3];
            } else {
                accA3[0] += acc[0]; accA3[1] += acc[1];
                accA3[2] += acc[2]; accA3[3] += acc[3];
            }
        }
        // no sync needed: GEMM3 output lives in registers; next act-fill only
        // touches sAct whose last readers finished before the post-h1 sync.
    }

    // ---- store p fragments once ----
    {
        int r0 = m0 + g, c0 = nt3 * 8 + 2 * t4;
        sPw[r0 * 16 + c0]           = accW3[0];
        sPw[r0 * 16 + c0 + 1]       = accW3[1];
        sPw[(r0 + 8) * 16 + c0]     = accW3[2];
        sPw[(r0 + 8) * 16 + c0 + 1] = accW3[3];
        sPa[r0 * 16 + c0]           = accA3[0];
        sPa[r0 * 16 + c0 + 1]       = accA3[1];
        sPa[(r0 + 8) * 16 + c0]     = accA3[2];
        sPa[(r0 + 8) * 16 + c0 + 1] = accA3[3];
    }
    __syncthreads();

    // ---- epilogue: per-row KL in f64 ----
    if (tid < MT) {
        const int r = tid;
        const double INV11 = 1.0 / 11.0;
        double pw[16], po[16];
#pragma unroll
        for (int a = 0; a < 16; a++) {
            pw[a] = (double)sPw[r * 16 + a];
            po[a] = (double)sPa[r * 16 + a] * INV11;
        }
        double mw = pw[0], mo = po[0];
#pragma unroll
        for (int a = 1; a < 16; a++) {
            mw = fmax(mw, pw[a]);
            mo = fmax(mo, po[a]);
        }
        double eo[16];
        double sw = 0.0, so = 0.0;
#pragma unroll
        for (int a = 0; a < 16; a++) {
            sw += fexp(pw[a] - mw);
            eo[a] = fexp(po[a] - mo);
            so += eo[a];
        }
        double lsw = flog(sw);
        double lso = flog(so);
        double inv_so = 1.0 / so;
        double infl = 0.0;
#pragma unroll
        for (int a = 0; a < 16; a++) {
            double q = eo[a] * inv_so;
            double logq = (po[a] - mo) - lso;
            double logp = (pw[a] - mw) - lsw;
            infl += q * (logq - logp);
        }
        g_infl[row0 + r] = infl;
    }
}

// ---------------- finalize: mean over N, normalize over T (f64) ----------------
__global__ void finalize_kernel(float* __restrict__ out) {
    const int b = blockIdx.x;
    const int tid = threadIdx.x;
    __shared__ double v[512];
    __shared__ double red[256];
    for (int t = tid; t < 512; t += 256) {
        const double* p = &g_infl[((size_t)b * 512 + t) * 10];
        double s = 0.0;
#pragma unroll
        for (int n = 0; n < 10; n++) s += p[n];
        v[t] = s;
    }
    __syncthreads();
    red[tid] = v[tid] + v[tid + 256];
    __syncthreads();
    for (int o = 128; o > 0; o >>= 1) {
        if (tid < o) red[tid] += red[tid + o];
        __syncthreads();
    }
    double tot = red[0];
    for (int t = tid; t < 512; t += 256)
        out[(size_t)b * 512 + t] = (float)(v[t] / tot);
}

// ---------------- launch ----------------
extern "C" void kernel_launch(void* const* d_in, const int* in_sizes, int n_in,
                              void* d_out, int out_size) {
    const float* obs     = (const float*)d_in[0];
    const float* actions = (const float*)d_in[1];
    const float* W1      = (const float*)d_in[2];
    const float* b1      = (const float*)d_in[3];
    const float* W2      = (const float*)d_in[4];
    const float* b2      = (const float*)d_in[5];
    const float* W3      = (const float*)d_in[6];
    const float* b3      = (const float*)d_in[7];

    cudaFuncSetAttribute(fused_kernel, cudaFuncAttributeMaxDynamicSharedMemorySize,
                         (int)SMEM_BYTES);
    fused_kernel<<<NTILES, 256, SMEM_BYTES>>>(obs, actions, W1, b1, W2, b2, W3, b3);
    finalize_kernel<<<32, 256>>>((float*)d_out);
}

// round 17
// speedup vs baseline: 1.9838x; 1.0724x over previous
#include <cuda_runtime.h>
#include <cstdint>
#include <math.h>

// Numerics: GEMM1 bit-frozen scalar fp32. delta & GEMM2 on tensor cores with
// 1xTF32 (delta-site noise bounded <=0.298e-3 via R3/R15 measurements; total
// worst-case sqrt(0.8454^2+0.298^2)=0.896e-3 < 1e-3). GEMM3 3xTF32 (~exact).
// PRNG: JAX partitionable threefry. Epilogue: fast f64, 4 threads/row.

// ---------------- problem constants ----------------
constexpr int NV = 12;
constexpr int R = 32 * 512 * 10;                      // 163840 rows
constexpr int MT = 64;
constexpr int NTILES = R / MT;                        // 2560
constexpr int STX = 132;
constexpr int STH = 68;
constexpr int STA = 20;                               // sAct stride (conflict-free)

// ---------------- smem layout (floats) ----------------
constexpr int OFF_W1 = 0;                     // [144][128]; rows 0-127 reused post-GEMM1
constexpr int OFF_W2 = OFF_W1 + 144 * 128;
constexpr int OFF_W3 = OFF_W2 + 128 * 64;
constexpr int OFF_B1 = OFF_W3 + 64 * 16;
constexpr int OFF_B2 = OFF_B1 + 128;
constexpr int OFF_B3 = OFF_B2 + 64;
constexpr int OFF_X  = OFF_B3 + 16;           // obs tile [64][132]; reused as W2bigT
constexpr int OFF_H1 = OFF_X + MT * STX;
constexpr int OFF_H2 = OFF_H1 + MT * STX;
constexpr int OFF_ACT = OFF_H2 + MT * STH;    // [64][20]
constexpr int OFF_PW = OFF_ACT + MT * STA;
constexpr int OFF_PA = OFF_PW + MT * 16;
constexpr int SMEM_FLOATS = OFF_PA + MT * 16;
constexpr size_t SMEM_BYTES = SMEM_FLOATS * sizeof(float); // ~210 KB

// reuse offsets inside dead W1 rows 0..127 region (16384 floats)
constexpr int ROFF_BASE  = 0;        // [64][132] = 8448
constexpr int ROFF_W1DB  = 8448;     // [128][20] = 2560
constexpr int ROFF_W3B   = 11008;    // [16][68]  = 1088
constexpr int ROFF_W3S   = 12096;    // [16][68]  = 1088  (ends 13184 < 16384)

__device__ double g_infl[R];

// ---------------- packed f32x2 helpers ----------------
typedef unsigned long long u64t;

__device__ __forceinline__ u64t pk2(float lo, float hi) {
    u64t d;
    asm("mov.b64 %0, {%1, %2};" : "=l"(d)
        : "r"(__float_as_uint(lo)), "r"(__float_as_uint(hi)));
    return d;
}
__device__ __forceinline__ void upk2(float& lo, float& hi, u64t s) {
    uint32_t a, b;
    asm("mov.b64 {%0, %1}, %2;" : "=r"(a), "=r"(b) : "l"(s));
    lo = __uint_as_float(a);
    hi = __uint_as_float(b);
}
__device__ __forceinline__ u64t fma2(u64t a, u64t b, u64t c) {
    u64t d;
    asm("fma.rn.f32x2 %0, %1, %2, %3;" : "=l"(d) : "l"(a), "l"(b), "l"(c));
    return d;
}

// ---------------- tf32 helpers ----------------
__device__ __forceinline__ uint32_t tf32bits(float x) {
    uint32_t u;
    asm("cvt.rna.tf32.f32 %0, %1;" : "=r"(u) : "f"(x));
    return u;
}

// mma.sync m16n8k8 tf32: d += a*b (f32 accumulate)
__device__ __forceinline__ void mma_tf32(float* d,
                                         uint32_t a0, uint32_t a1, uint32_t a2, uint32_t a3,
                                         uint32_t b0, uint32_t b1) {
    asm volatile(
        "mma.sync.aligned.m16n8k8.row.col.f32.tf32.tf32.f32 "
        "{%0,%1,%2,%3}, {%4,%5,%6,%7}, {%8,%9}, {%0,%1,%2,%3};"
        : "+f"(d[0]), "+f"(d[1]), "+f"(d[2]), "+f"(d[3])
        : "r"(a0), "r"(a1), "r"(a2), "r"(a3), "r"(b0), "r"(b1));
}

// ---------------- fast f64 exp/log (err ~1e-13, args bounded) ----------------
__device__ __forceinline__ double fexp(double x) {
    double n = floor(fma(x, 1.4426950408889634, 0.5));
    double r = fma(n, -6.93147180369123816490e-01, x);
    r = fma(n, -1.90821492927058770002e-10, r);
    double p = 2.5052108385441718775e-8;
    p = fma(p, r, 2.7557319223985890653e-7);
    p = fma(p, r, 2.7557319223985892511e-6);
    p = fma(p, r, 2.4801587301587301566e-5);
    p = fma(p, r, 1.9841269841269841253e-4);
    p = fma(p, r, 1.3888888888888889419e-3);
    p = fma(p, r, 8.3333333333333332177e-3);
    p = fma(p, r, 4.1666666666666664354e-2);
    p = fma(p, r, 1.6666666666666665741e-1);
    p = fma(p, r, 5.0e-1);
    p = fma(p, r, 1.0);
    p = fma(p, r, 1.0);
    int ni = (int)n;
    double two_n = __longlong_as_double((long long)(1023 + ni) << 52);
    return p * two_n;
}

__device__ __forceinline__ double flog(double x) {
    long long b = __double_as_longlong(x);
    int e = (int)(b >> 52) - 1022;
    double m = __longlong_as_double((b & 0x000FFFFFFFFFFFFFLL) | 0x3FE0000000000000LL);
    if (m < 0.70710678118654752440) { m = m + m; e -= 1; }
    double f = m - 1.0;
    double s = f / (f + 2.0);
    double z = s * s;
    double p = 0.15384615384615385469;
    p = fma(p, z, 0.18181818181818182323);
    p = fma(p, z, 0.22222222222222220989);
    p = fma(p, z, 0.28571428571428569843);
    p = fma(p, z, 0.40000000000000002220);
    p = fma(p, z, 0.66666666666666662966);
    p = fma(p, z, 2.0);
    double lm = s * p;
    return fma((double)e, 0.69314718055994530942, lm);
}

// ---------------- threefry2x32 (20 rounds, JAX-exact) ----------------
__device__ __forceinline__ void tf2x32(uint32_t k0, uint32_t k1,
                                       uint32_t c0, uint32_t c1,
                                       uint32_t& o0, uint32_t& o1) {
    uint32_t ks2 = k0 ^ k1 ^ 0x1BD11BDAu;
    uint32_t x0 = c0 + k0, x1 = c1 + k1;
#define TF_R(r) { x0 += x1; x1 = (x1 << (r)) | (x1 >> (32 - (r))); x1 ^= x0; }
    TF_R(13) TF_R(15) TF_R(26) TF_R(6)
    x0 += k1;  x1 += ks2 + 1u;
    TF_R(17) TF_R(29) TF_R(16) TF_R(24)
    x0 += ks2; x1 += k0 + 2u;
    TF_R(13) TF_R(15) TF_R(26) TF_R(6)
    x0 += k0;  x1 += k1 + 3u;
    TF_R(17) TF_R(29) TF_R(16) TF_R(24)
    x0 += k1;  x1 += ks2 + 4u;
    TF_R(13) TF_R(15) TF_R(26) TF_R(6)
    x0 += ks2; x1 += k0 + 5u;
#undef TF_R
    o0 = x0; o1 = x1;
}

__device__ __forceinline__ float u01(uint32_t bits) {
    return __uint_as_float((bits >> 9) | 0x3F800000u) - 1.0f;
}

// ---------------- fused kernel ----------------
__global__ __launch_bounds__(256, 1)
void fused_kernel(const float* __restrict__ obs, const float* __restrict__ actions,
                  const float* __restrict__ W1, const float* __restrict__ b1,
                  const float* __restrict__ W2, const float* __restrict__ b2,
                  const float* __restrict__ W3, const float* __restrict__ b3) {
    extern __shared__ float sm[];
    float* sW1 = sm + OFF_W1;
    float* sW2 = sm + OFF_W2;
    float* sW3 = sm + OFF_W3;
    float* sB1 = sm + OFF_B1;
    float* sB2 = sm + OFF_B2;
    float* sB3 = sm + OFF_B3;
    float* sX  = sm + OFF_X;
    float* sH1 = sm + OFF_H1;
    float* sH2 = sm + OFF_H2;
    float* sAct = sm + OFF_ACT;
    float* sPw = sm + OFF_PW;
    float* sPa = sm + OFF_PA;
    // post-GEMM1 reuse
    float* W2bigT = sX;                    // tf32 W2^T [col][k], stride 132
    float* sBase  = sW1 + ROFF_BASE;       // h1_base [64][132]
    float* W1dBig = sW1 + ROFF_W1DB;       // tf32 W1[128:144]^T [col][k] stride 20
    float* W3Big  = sW1 + ROFF_W3B;        // W3^T big [col][k] stride 68
    float* W3Sml  = sW1 + ROFF_W3S;

    const int tid = threadIdx.x;

    {
        const float4* s; float4* d;
        s = (const float4*)W1; d = (float4*)sW1;
        for (int i = tid; i < 144 * 128 / 4; i += 256) d[i] = s[i];
        s = (const float4*)W2; d = (float4*)sW2;
        for (int i = tid; i < 128 * 64 / 4; i += 256) d[i] = s[i];
        s = (const float4*)W3; d = (float4*)sW3;
        for (int i = tid; i < 64 * 16 / 4; i += 256) d[i] = s[i];
        s = (const float4*)b1; d = (float4*)sB1;
        for (int i = tid; i < 32; i += 256) d[i] = s[i];
        s = (const float4*)b2; d = (float4*)sB2;
        if (tid < 16) d[tid] = s[tid];
        s = (const float4*)b3; d = (float4*)sB3;
        if (tid < 4) d[tid] = s[tid];
    }

    const int row0 = blockIdx.x * MT;

    for (int i = tid; i < MT * 32; i += 256) {
        int r = i >> 5, c4 = i & 31;
        float4 v = ((const float4*)obs)[(size_t)(row0 + r) * 32 + c4];
        *(float4*)&sX[r * STX + c4 * 4] = v;
    }
    __syncthreads();

    const int tx = tid & 15;
    const int ty = tid >> 4;
    const int wid = tid >> 5;
    const int lane = tid & 31;
    const int g = lane >> 2;      // mma group id
    const int t4 = lane & 3;      // mma thread-in-group

    // ---- GEMM1: base = obs @ W1[:128] + b1 (bit-frozen scalar) ----
    u64t base2[4][4];
    {
        u64t bp[4];
#pragma unroll
        for (int j = 0; j < 4; j++)
            bp[j] = pk2(sB1[tx * 8 + 2 * j], sB1[tx * 8 + 2 * j + 1]);
#pragma unroll
        for (int i = 0; i < 4; i++)
#pragma unroll
            for (int j = 0; j < 4; j++) base2[i][j] = bp[j];
    }

    for (int k4 = 0; k4 < 128; k4 += 4) {
        float4 A0 = *(const float4*)&sX[(ty * 4 + 0) * STX + k4];
        float4 A1 = *(const float4*)&sX[(ty * 4 + 1) * STX + k4];
        float4 A2 = *(const float4*)&sX[(ty * 4 + 2) * STX + k4];
        float4 A3 = *(const float4*)&sX[(ty * 4 + 3) * STX + k4];
#pragma unroll
        for (int kk = 0; kk < 4; kk++) {
            const ulonglong2* wp = (const ulonglong2*)&sW1[(k4 + kk) * 128 + tx * 8];
            ulonglong2 wA = wp[0], wB = wp[1];
            float a0 = (&A0.x)[kk], a1 = (&A1.x)[kk], a2 = (&A2.x)[kk], a3 = (&A3.x)[kk];
            u64t p0 = pk2(a0, a0), p1 = pk2(a1, a1), p2 = pk2(a2, a2), p3 = pk2(a3, a3);
            base2[0][0] = fma2(p0, wA.x, base2[0][0]); base2[0][1] = fma2(p0, wA.y, base2[0][1]);
            base2[0][2] = fma2(p0, wB.x, base2[0][2]); base2[0][3] = fma2(p0, wB.y, base2[0][3]);
            base2[1][0] = fma2(p1, wA.x, base2[1][0]); base2[1][1] = fma2(p1, wA.y, base2[1][1]);
            base2[1][2] = fma2(p1, wB.x, base2[1][2]); base2[1][3] = fma2(p1, wB.y, base2[1][3]);
            base2[2][0] = fma2(p2, wA.x, base2[2][0]); base2[2][1] = fma2(p2, wA.y, base2[2][1]);
            base2[2][2] = fma2(p2, wB.x, base2[2][2]); base2[2][3] = fma2(p2, wB.y, base2[2][3]);
            base2[3][0] = fma2(p3, wA.x, base2[3][0]); base2[3][1] = fma2(p3, wA.y, base2[3][1]);
            base2[3][2] = fma2(p3, wB.x, base2[3][2]); base2[3][3] = fma2(p3, wB.y, base2[3][3]);
        }
    }
    __syncthreads();   // all reads of sX (obs) and sW1 rows 0-127 complete

    // ---- one-time prep: base -> smem; tf32 tables for W2, W1delta, W3 ----
#pragma unroll
    for (int i = 0; i < 4; i++)
#pragma unroll
        for (int j = 0; j < 4; j++) {
            float lo, hi;
            upk2(lo, hi, base2[i][j]);
            sBase[(ty * 4 + i) * STX + tx * 8 + 2 * j]     = lo;
            sBase[(ty * 4 + i) * STX + tx * 8 + 2 * j + 1] = hi;
        }
    for (int idx = tid; idx < 128 * 64; idx += 256) {
        int k = idx >> 6, c = idx & 63;
        W2bigT[c * 132 + k] = __uint_as_float(tf32bits(sW2[k * 64 + c]));
    }
    for (int idx = tid; idx < 128 * 16; idx += 256) {
        int col = idx >> 4, k = idx & 15;
        W1dBig[col * STA + k] = __uint_as_float(tf32bits(sW1[(128 + k) * 128 + col]));
    }
    for (int idx = tid; idx < 16 * 64; idx += 256) {
        int col = idx >> 6, k = idx & 63;
        float w = sW3[k * 16 + col];
        float big = __uint_as_float(tf32bits(w));
        W3Big[col * STH + k] = big;
        W3Sml[col * STH + k] = __uint_as_float(tf32bits(w - big));
    }
    __syncthreads();

    // warp tilings
    const int m0 = (wid & 3) * 16;       // shared m-tile
    const int n0g2 = (wid >> 2) * 32;    // GEMM2 n-range
    const int nbd = (wid >> 2) * 64;     // delta n-range
    const int nt3 = (wid >> 2);          // GEMM3 n-tile

    float accW3[4], accA3[4];

    // ---- variant loop ----
    for (int v = 0; v < NV; v++) {
        if (v == 0) {
            for (int i = tid; i < MT * 4; i += 256) {
                int r = i >> 2, c4 = i & 3;
                *(float4*)&sAct[r * STA + c4 * 4] =
                    ((const float4*)actions)[(size_t)row0 * 4 + i];
            }
        } else if (v == 1) {
            for (int i = tid; i < MT * STA; i += 256) sAct[i] = 0.0f;
        } else {
            uint32_t s = (uint32_t)(v - 2);
            uint32_t k0, k1;
            tf2x32(0u, 1u, 0u, s, k0, k1);   // key_s = threefry(key(1), (0,s))
            for (int i = tid; i < MT * 16; i += 256) {
                uint32_t gi = (uint32_t)row0 * 16u + (uint32_t)i;
                uint32_t o0, o1;
                tf2x32(k0, k1, 0u, gi, o0, o1);
                sAct[(i >> 4) * STA + (i & 15)] = u01(o0 ^ o1);
            }
        }
        __syncthreads();

        // ---- delta on tensor cores (1xTF32): h1 = relu(base + act@W1d),
        //      stored pre-rounded to tf32 grid (identical to GEMM2's rounding) ----
        {
            uint32_t Ab[2][4];
#pragma unroll
            for (int s = 0; s < 2; s++) {
                int k0 = s * 8;
                Ab[s][0] = tf32bits(sAct[(m0 + g) * STA + k0 + t4]);
                Ab[s][1] = tf32bits(sAct[(m0 + g + 8) * STA + k0 + t4]);
                Ab[s][2] = tf32bits(sAct[(m0 + g) * STA + k0 + t4 + 4]);
                Ab[s][3] = tf32bits(sAct[(m0 + g + 8) * STA + k0 + t4 + 4]);
            }
#pragma unroll
            for (int j = 0; j < 8; j++) {
                int cj = nbd + j * 8;
                float acc[4];
                acc[0] = sBase[(m0 + g) * STX + cj + 2 * t4];
                acc[1] = sBase[(m0 + g) * STX + cj + 2 * t4 + 1];
                acc[2] = sBase[(m0 + g + 8) * STX + cj + 2 * t4];
                acc[3] = sBase[(m0 + g + 8) * STX + cj + 2 * t4 + 1];
                int colb = cj + g;
#pragma unroll
                for (int s = 0; s < 2; s++) {
                    int k0 = s * 8;
                    uint32_t bb0 = __float_as_uint(W1dBig[colb * STA + k0 + t4]);
                    uint32_t bb1 = __float_as_uint(W1dBig[colb * STA + k0 + t4 + 4]);
                    mma_tf32(acc, Ab[s][0], Ab[s][1], Ab[s][2], Ab[s][3], bb0, bb1);
                }
                sH1[(m0 + g) * STX + cj + 2 * t4] =
                    __uint_as_float(tf32bits(fmaxf(acc[0], 0.0f)));
                sH1[(m0 + g) * STX + cj + 2 * t4 + 1] =
                    __uint_as_float(tf32bits(fmaxf(acc[1], 0.0f)));
                sH1[(m0 + g + 8) * STX + cj + 2 * t4] =
                    __uint_as_float(tf32bits(fmaxf(acc[2], 0.0f)));
                sH1[(m0 + g + 8) * STX + cj + 2 * t4 + 1] =
                    __uint_as_float(tf32bits(fmaxf(acc[3], 0.0f)));
            }
        }
        __syncthreads();

        // ---- GEMM2 on tensor cores: h2 = relu(h1 @ W2 + b2), 1xTF32 ----
        {
            float acc[4][4];
#pragma unroll
            for (int j = 0; j < 4; j++) {
                int col0 = n0g2 + j * 8 + 2 * t4;
                acc[j][0] = sB2[col0];
                acc[j][1] = sB2[col0 + 1];
                acc[j][2] = acc[j][0];
                acc[j][3] = acc[j][1];
            }
#pragma unroll 4
            for (int s = 0; s < 16; s++) {
                int k0 = s * 8;
                uint32_t ua0 = __float_as_uint(sH1[(m0 + g) * STX + k0 + t4]);
                uint32_t ua1 = __float_as_uint(sH1[(m0 + g + 8) * STX + k0 + t4]);
                uint32_t ua2 = __float_as_uint(sH1[(m0 + g) * STX + k0 + t4 + 4]);
                uint32_t ua3 = __float_as_uint(sH1[(m0 + g + 8) * STX + k0 + t4 + 4]);
#pragma unroll
                for (int j = 0; j < 4; j++) {
                    int col = n0g2 + j * 8 + g;
                    uint32_t bb0 = __float_as_uint(W2bigT[col * 132 + k0 + t4]);
                    uint32_t bb1 = __float_as_uint(W2bigT[col * 132 + k0 + t4 + 4]);
                    mma_tf32(acc[j], ua0, ua1, ua2, ua3, bb0, bb1);
                }
            }
#pragma unroll
            for (int j = 0; j < 4; j++) {
                int col0 = n0g2 + j * 8 + 2 * t4;
                sH2[(m0 + g) * STH + col0]         = fmaxf(acc[j][0], 0.0f);
                sH2[(m0 + g) * STH + col0 + 1]     = fmaxf(acc[j][1], 0.0f);
                sH2[(m0 + g + 8) * STH + col0]     = fmaxf(acc[j][2], 0.0f);
                sH2[(m0 + g + 8) * STH + col0 + 1] = fmaxf(acc[j][3], 0.0f);
            }
        }
        __syncthreads();

        // ---- GEMM3 on tensor cores (3xTF32): p = h2 @ W3 + b3, reg accumulate ----
        {
            float acc[4];
            int c0 = nt3 * 8 + 2 * t4;
            acc[0] = sB3[c0];
            acc[1] = sB3[c0 + 1];
            acc[2] = acc[0];
            acc[3] = acc[1];
            int colb = nt3 * 8 + g;
#pragma unroll
            for (int s = 0; s < 8; s++) {
                int k0 = s * 8;
                float a0 = sH2[(m0 + g) * STH + k0 + t4];
                float a1 = sH2[(m0 + g + 8) * STH + k0 + t4];
                float a2 = sH2[(m0 + g) * STH + k0 + t4 + 4];
                float a3 = sH2[(m0 + g + 8) * STH + k0 + t4 + 4];
                uint32_t ab0 = tf32bits(a0), as0 = tf32bits(a0 - __uint_as_float(ab0));
                uint32_t ab1 = tf32bits(a1), as1 = tf32bits(a1 - __uint_as_float(ab1));
                uint32_t ab2 = tf32bits(a2), as2 = tf32bits(a2 - __uint_as_float(ab2));
                uint32_t ab3 = tf32bits(a3), as3 = tf32bits(a3 - __uint_as_float(ab3));
                uint32_t bb0 = __float_as_uint(W3Big[colb * STH + k0 + t4]);
                uint32_t bb1 = __float_as_uint(W3Big[colb * STH + k0 + t4 + 4]);
                uint32_t bs0 = __float_as_uint(W3Sml[colb * STH + k0 + t4]);
                uint32_t bs1 = __float_as_uint(W3Sml[colb * STH + k0 + t4 + 4]);
                mma_tf32(acc, ab0, ab1, ab2, ab3, bb0, bb1);
                mma_tf32(acc, as0, as1, as2, as3, bb0, bb1);
                mma_tf32(acc, ab0, ab1, ab2, ab3, bs0, bs1);
            }
            if (v == 0) {
                accW3[0] = acc[0]; accW3[1] = acc[1]; accW3[2] = acc[2]; accW3[3] = acc[3];
            } else if (v == 1) {
                accA3[0] = acc[0]; accA3[1] = acc[1]; accA3[2] = acc[2]; accA3[3] = acc[3];
            } else {
                accA3[0] += acc[0]; accA3[1] += acc[1];
                accA3[2] += acc[2]; accA3[3] += acc[3];
            }
        }
        // no sync needed: GEMM3 output lives in registers.
    }

    // ---- store p fragments once ----
    {
        int r0 = m0 + g, c0 = nt3 * 8 + 2 * t4;
        sPw[r0 * 16 + c0]           = accW3[0];
        sPw[r0 * 16 + c0 + 1]       = accW3[1];
        sPw[(r0 + 8) * 16 + c0]     = accW3[2];
        sPw[(r0 + 8) * 16 + c0 + 1] = accW3[3];
        sPa[r0 * 16 + c0]           = accA3[0];
        sPa[r0 * 16 + c0 + 1]       = accA3[1];
        sPa[(r0 + 8) * 16 + c0]     = accA3[2];
        sPa[(r0 + 8) * 16 + c0 + 1] = accA3[3];
    }
    __syncthreads();

    // ---- epilogue: per-row KL in f64, 4 threads per row ----
    {
        const int r = tid >> 2;
        const int q4 = tid & 3;
        const double INV11 = 1.0 / 11.0;
        double pw[4], po[4];
#pragma unroll
        for (int a = 0; a < 4; a++) {
            int col = q4 * 4 + a;
            pw[a] = (double)sPw[r * 16 + col];
            po[a] = (double)sPa[r * 16 + col] * INV11;
        }
        double mw = fmax(fmax(pw[0], pw[1]), fmax(pw[2], pw[3]));
        double mo = fmax(fmax(po[0], po[1]), fmax(po[2], po[3]));
        mw = fmax(mw, __shfl_xor_sync(0xFFFFFFFFu, mw, 1));
        mw = fmax(mw, __shfl_xor_sync(0xFFFFFFFFu, mw, 2));
        mo = fmax(mo, __shfl_xor_sync(0xFFFFFFFFu, mo, 1));
        mo = fmax(mo, __shfl_xor_sync(0xFFFFFFFFu, mo, 2));
        double eo[4];
        double sw = 0.0, so = 0.0;
#pragma unroll
        for (int a = 0; a < 4; a++) {
            sw += fexp(pw[a] - mw);
            eo[a] = fexp(po[a] - mo);
            so += eo[a];
        }
        sw += __shfl_xor_sync(0xFFFFFFFFu, sw, 1);
        sw += __shfl_xor_sync(0xFFFFFFFFu, sw, 2);
        so += __shfl_xor_sync(0xFFFFFFFFu, so, 1);
        so += __shfl_xor_sync(0xFFFFFFFFu, so, 2);
        double lsw = flog(sw);
        double lso = flog(so);
        double inv_so = 1.0 / so;
        double infl = 0.0;
#pragma unroll
        for (int a = 0; a < 4; a++) {
            double q = eo[a] * inv_so;
            double logq = (po[a] - mo) - lso;
            double logp = (pw[a] - mw) - lsw;
            infl += q * (logq - logp);
        }
        infl += __shfl_xor_sync(0xFFFFFFFFu, infl, 1);
        infl += __shfl_xor_sync(0xFFFFFFFFu, infl, 2);
        if (q4 == 0) g_infl[row0 + r] = infl;
    }
}

// ---------------- finalize: mean over N, normalize over T (f64) ----------------
__global__ void finalize_kernel(float* __restrict__ out) {
    const int b = blockIdx.x;
    const int tid = threadIdx.x;
    __shared__ double v[512];
    __shared__ double red[256];
    for (int t = tid; t < 512; t += 256) {
        const double* p = &g_infl[((size_t)b * 512 + t) * 10];
        double s = 0.0;
#pragma unroll
        for (int n = 0; n < 10; n++) s += p[n];
        v[t] = s;
    }
    __syncthreads();
    red[tid] = v[tid] + v[tid + 256];
    __syncthreads();
    for (int o = 128; o > 0; o >>= 1) {
        if (tid < o) red[tid] += red[tid + o];
        __syncthreads();
    }
    double tot = red[0];
    for (int t = tid; t < 512; t += 256)
        out[(size_t)b * 512 + t] = (float)(v[t] / tot);
}

// ---------------- launch ----------------
extern "C" void kernel_launch(void* const* d_in, const int* in_sizes, int n_in,
                              void* d_out, int out_size) {
    const float* obs     = (const float*)d_in[0];
    const float* actions = (const float*)d_in[1];
    const float* W1      = (const float*)d_in[2];
    const float* b1      = (const float*)d_in[3];
    const float* W2      = (const float*)d_in[4];
    const float* b2      = (const float*)d_in[5];
    const float* W3      = (const float*)d_in[6];
    const float* b3      = (const float*)d_in[7];

    cudaFuncSetAttribute(fused_kernel, cudaFuncAttributeMaxDynamicSharedMemorySize,
                         (int)SMEM_BYTES);
    fused_kernel<<<NTILES, 256, SMEM_BYTES>>>(obs, actions, W1, b1, W2, b2, W3, b3);
    finalize_kernel<<<32, 256>>>((float*)d_out);
}